// round 3
// baseline (speedup 1.0000x reference)
#include <cuda_runtime.h>
#include <cstdint>
#include <cstddef>

// Problem constants
#define BB   256
#define HN   12
#define N1   12
#define DD   1024            // dim == inner == 1024
#define BH   (BB*HN)         // 3072
#define M1   (BH*N1)         // 36864 rows (per stream)
#define M2   (BH*2*N1)       // 73728 rows (concat streams)

#define S1   ((size_t)M1 * DD)   // 37,748,736 floats per stream-tensor

// ---------------------------------------------------------------------------
// Single scratch arena with aliased regions (stream-ordered reuse):
//   [0*S1 .. 2*S1) : emb_r, emb_t      -> later reused as ctx_r, ctx_t
//   [2*S1 .. 4*S1) : lnin (2 streams)  -> later reused as q_r, q_t
//   [4*S1 .. 6*S1) : key
//   [6*S1 .. 8*S1) : val
// ---------------------------------------------------------------------------
__device__ float g_scratch[8 * S1];

__device__ float g_bn_sum[2][12];
__device__ float g_bn_sq [2][12];
__device__ float g_bn_scale[2][12];
__device__ float g_bn_shift[2][12];

// ---------------------------------------------------------------------------
// GEMM: C[M,1024] = A[M,1024] @ W[1024,1024]^T + bias
// MODE 0: A row r -> A0 + r*1024
// MODE 1: A row r -> concat over j=r%24 of (A0: j<12) / (A1: j>=12), bh=r/24
// Tiles: BM=BN=128, BK=16, 256 threads, 8x8 per-thread micro-tile.
// ---------------------------------------------------------------------------
template<int MODE>
__device__ __forceinline__ const float* a_rowptr(const float* A0, const float* A1, int gr) {
    if (MODE == 0) return A0 + (size_t)gr * DD;
    int bh = gr / 24, j = gr % 24;
    const float* base = (j < 12) ? A0 : A1;
    return base + ((size_t)bh * 12 + (j % 12)) * DD;
}

template<int MODE>
__global__ __launch_bounds__(256) void gemm_tn(
    const float* __restrict__ A0, const float* __restrict__ A1,
    const float* __restrict__ W, const float* __restrict__ bias,
    float* __restrict__ C)
{
    __shared__ float As[16][128];
    __shared__ float Bs[16][128];

    const int tid = threadIdx.x;
    const int bm  = blockIdx.y * 128;
    const int bn  = blockIdx.x * 128;
    const int tx  = tid & 15;
    const int ty  = tid >> 4;

    const int lrow = tid >> 2;        // 0..63
    const int lk   = (tid & 3) << 2;  // 0,4,8,12

    const float* a0p = a_rowptr<MODE>(A0, A1, bm + lrow)      + lk;
    const float* a1p = a_rowptr<MODE>(A0, A1, bm + lrow + 64) + lk;
    const float* w0p = W + (size_t)(bn + lrow)      * DD + lk;
    const float* w1p = W + (size_t)(bn + lrow + 64) * DD + lk;

    float acc[8][8];
    #pragma unroll
    for (int i = 0; i < 8; i++)
        #pragma unroll
        for (int j = 0; j < 8; j++) acc[i][j] = 0.f;

    for (int kt = 0; kt < DD; kt += 16) {
        float4 a0 = *(const float4*)(a0p + kt);
        float4 a1 = *(const float4*)(a1p + kt);
        float4 w0 = *(const float4*)(w0p + kt);
        float4 w1 = *(const float4*)(w1p + kt);
        __syncthreads();
        As[lk+0][lrow] = a0.x; As[lk+1][lrow] = a0.y; As[lk+2][lrow] = a0.z; As[lk+3][lrow] = a0.w;
        As[lk+0][lrow+64] = a1.x; As[lk+1][lrow+64] = a1.y; As[lk+2][lrow+64] = a1.z; As[lk+3][lrow+64] = a1.w;
        Bs[lk+0][lrow] = w0.x; Bs[lk+1][lrow] = w0.y; Bs[lk+2][lrow] = w0.z; Bs[lk+3][lrow] = w0.w;
        Bs[lk+0][lrow+64] = w1.x; Bs[lk+1][lrow+64] = w1.y; Bs[lk+2][lrow+64] = w1.z; Bs[lk+3][lrow+64] = w1.w;
        __syncthreads();
        #pragma unroll
        for (int k = 0; k < 16; k++) {
            float af[8], wf[8];
            *(float4*)&af[0] = *(const float4*)&As[k][ty*8];
            *(float4*)&af[4] = *(const float4*)&As[k][ty*8+4];
            *(float4*)&wf[0] = *(const float4*)&Bs[k][tx*8];
            *(float4*)&wf[4] = *(const float4*)&Bs[k][tx*8+4];
            #pragma unroll
            for (int i = 0; i < 8; i++)
                #pragma unroll
                for (int j = 0; j < 8; j++)
                    acc[i][j] += af[i] * wf[j];
        }
    }

    float bl[8];
    #pragma unroll
    for (int j = 0; j < 8; j++) bl[j] = bias[bn + tx*8 + j];
    #pragma unroll
    for (int i = 0; i < 8; i++) {
        float* crow = C + (size_t)(bm + ty*8 + i) * DD + bn + tx*8;
        float4 v0, v1;
        v0.x = acc[i][0]+bl[0]; v0.y = acc[i][1]+bl[1]; v0.z = acc[i][2]+bl[2]; v0.w = acc[i][3]+bl[3];
        v1.x = acc[i][4]+bl[4]; v1.y = acc[i][5]+bl[5]; v1.z = acc[i][6]+bl[6]; v1.w = acc[i][7]+bl[7];
        *(float4*)(crow)     = v0;
        *(float4*)(crow + 4) = v1;
    }
}

// ---------------------------------------------------------------------------
// BatchNorm (channel = row % 12, stats over 3072*1024 elements per channel)
// ---------------------------------------------------------------------------
__global__ void bn_zero_kernel() {
    int t = threadIdx.x;
    if (t < 24) { ((float*)g_bn_sum)[t] = 0.f; ((float*)g_bn_sq)[t] = 0.f; }
}

// grid.x = M1, grid.y = 2 (stream index); x0/x1 = emb_r/emb_t
__global__ __launch_bounds__(256) void bn_stats_kernel(const float* __restrict__ x0,
                                                       const float* __restrict__ x1) {
    int row  = blockIdx.x;
    int sidx = blockIdx.y;
    int tid  = threadIdx.x;
    const float* x = sidx ? x1 : x0;
    float4 v = ((const float4*)(x + (size_t)row * DD))[tid];
    float s = v.x + v.y + v.z + v.w;
    float q = v.x*v.x + v.y*v.y + v.z*v.z + v.w*v.w;
    #pragma unroll
    for (int o = 16; o > 0; o >>= 1) {
        s += __shfl_xor_sync(~0u, s, o);
        q += __shfl_xor_sync(~0u, q, o);
    }
    __shared__ float ss[8], qq[8];
    if ((tid & 31) == 0) { ss[tid >> 5] = s; qq[tid >> 5] = q; }
    __syncthreads();
    if (tid == 0) {
        float S = 0.f, Q = 0.f;
        #pragma unroll
        for (int w = 0; w < 8; w++) { S += ss[w]; Q += qq[w]; }
        atomicAdd(&g_bn_sum[sidx][row % 12], S);
        atomicAdd(&g_bn_sq [sidx][row % 12], Q);
    }
}

__global__ void bn_finalize_kernel(const float* __restrict__ bn_w, const float* __restrict__ bn_b) {
    int t = threadIdx.x;
    if (t < 24) {
        int s = t / 12, c = t % 12;
        const float CNT = 3072.0f * 1024.0f;
        float mean = g_bn_sum[s][c] / CNT;
        float var  = g_bn_sq [s][c] / CNT - mean * mean;
        float rstd = rsqrtf(var + 1e-5f);
        float sc   = rstd * bn_w[c];
        g_bn_scale[s][c] = sc;
        g_bn_shift[s][c] = bn_b[c] - mean * sc;
    }
}

// y = x*scale_c + shift_c + pos[b, n1, :]   (in place), row = b*144 + h*12 + n1
// grid.x = M1, grid.y = 2
__global__ __launch_bounds__(256) void bn_apply_kernel(float* __restrict__ x0,
                                                       float* __restrict__ x1,
                                                       const float* __restrict__ pos) {
    int row  = blockIdx.x;
    int sidx = blockIdx.y;
    int tid  = threadIdx.x;
    float* x = sidx ? x1 : x0;
    int c = row % 12;           // n1 == channel
    int b = row / 144;
    float sc = g_bn_scale[sidx][c], sh = g_bn_shift[sidx][c];
    float4 p = ((const float4*)(pos + ((size_t)(b * 12 + c)) * DD))[tid];
    float4* xp = (float4*)(x + (size_t)row * DD) + tid;
    float4 v = *xp;
    v.x = v.x * sc + sh + p.x;
    v.y = v.y * sc + sh + p.y;
    v.z = v.z * sc + sh + p.z;
    v.w = v.w * sc + sh + p.w;
    *xp = v;
}

// ---------------------------------------------------------------------------
// LayerNorm of concat(ar, at) along seq -> lnin, one block per output row
// ---------------------------------------------------------------------------
__global__ __launch_bounds__(256) void ln_kernel(const float* __restrict__ ar,
                                                 const float* __restrict__ at,
                                                 const float* __restrict__ lnw,
                                                 const float* __restrict__ lnb,
                                                 float* __restrict__ out) {
    int row = blockIdx.x;          // 0..M2-1
    int tid = threadIdx.x;
    int bh = row / 24, j = row % 24;
    const float* src = (j < 12) ? ar + ((size_t)bh * 12 + j) * DD
                                : at + ((size_t)bh * 12 + (j - 12)) * DD;
    float4 v = ((const float4*)src)[tid];
    float s = v.x + v.y + v.z + v.w;
    float q = v.x*v.x + v.y*v.y + v.z*v.z + v.w*v.w;
    #pragma unroll
    for (int o = 16; o > 0; o >>= 1) {
        s += __shfl_xor_sync(~0u, s, o);
        q += __shfl_xor_sync(~0u, q, o);
    }
    __shared__ float ss[8], qq[8], mom[2];
    if ((tid & 31) == 0) { ss[tid >> 5] = s; qq[tid >> 5] = q; }
    __syncthreads();
    if (tid == 0) {
        float S = 0.f, Q = 0.f;
        #pragma unroll
        for (int w = 0; w < 8; w++) { S += ss[w]; Q += qq[w]; }
        float mean = S / 1024.0f;
        float var  = Q / 1024.0f - mean * mean;
        mom[0] = mean;
        mom[1] = rsqrtf(var + 1e-5f);
    }
    __syncthreads();
    float mean = mom[0], rstd = mom[1];
    float4 w = ((const float4*)lnw)[tid];
    float4 bb = ((const float4*)lnb)[tid];
    float4 o4;
    o4.x = (v.x - mean) * rstd * w.x + bb.x;
    o4.y = (v.y - mean) * rstd * w.y + bb.y;
    o4.z = (v.z - mean) * rstd * w.z + bb.z;
    o4.w = (v.w - mean) * rstd * w.w + bb.w;
    ((float4*)(out + (size_t)row * DD))[tid] = o4;
}

// ---------------------------------------------------------------------------
// Fused attention: per bh, q(12 rgb + 12 tir) x k(24) logits, softmax, @v.
// smem: 24*1024 float staging (K then V) + 24*24 probs. ~101 KB dynamic.
// ---------------------------------------------------------------------------
#define ATTN_SMEM ((24*1024 + 24*24) * sizeof(float))

__global__ __launch_bounds__(256) void attn_kernel(
    const float* __restrict__ qr, const float* __restrict__ qt,
    const float* __restrict__ key, const float* __restrict__ val,
    float* __restrict__ ctx_r, float* __restrict__ ctx_t) {
    extern __shared__ float sm[];
    float* ks = sm;              // 24*1024 (K, later reused for V)
    float* at = sm + 24 * 1024;  // 24*24 logits -> probs

    int bh  = blockIdx.x;
    int tid = threadIdx.x;
    int warp = tid >> 5, lane = tid & 31;

    // Stage K
    const float* kbase = key + (size_t)bh * 24 * DD;
    for (int i = tid; i < 24 * DD / 4; i += 256)
        ((float4*)ks)[i] = ((const float4*)kbase)[i];
    __syncthreads();

    // Logits: warp w handles q rows [3w, 3w+3)
    for (int qi = warp * 3; qi < warp * 3 + 3; qi++) {
        const float* qrow = (qi < 12) ? qr + ((size_t)bh * 12 + qi) * DD
                                      : qt + ((size_t)bh * 12 + (qi - 12)) * DD;
        float qv[32];
        #pragma unroll
        for (int t = 0; t < 32; t++) qv[t] = qrow[t * 32 + lane];
        for (int j = 0; j < 24; j++) {
            float s = 0.f;
            #pragma unroll
            for (int t = 0; t < 32; t++) s += qv[t] * ks[j * DD + t * 32 + lane];
            #pragma unroll
            for (int o = 16; o > 0; o >>= 1) s += __shfl_xor_sync(~0u, s, o);
            if (lane == 0) at[qi * 24 + j] = s * 0.03125f;  // 1/sqrt(1024)
        }
    }
    __syncthreads();

    // Softmax per q-row (24 entries)
    for (int qi = warp * 3; qi < warp * 3 + 3; qi++) {
        float v = (lane < 24) ? at[qi * 24 + lane] : -3.0e38f;
        float m = v;
        #pragma unroll
        for (int o = 16; o > 0; o >>= 1) m = fmaxf(m, __shfl_xor_sync(~0u, m, o));
        float e = (lane < 24) ? expf(v - m) : 0.f;
        float s = e;
        #pragma unroll
        for (int o = 16; o > 0; o >>= 1) s += __shfl_xor_sync(~0u, s, o);
        if (lane < 24) at[qi * 24 + lane] = e / s;
    }
    __syncthreads();

    // Stage V (reuse ks)
    const float* vbase = val + (size_t)bh * 24 * DD;
    for (int i = tid; i < 24 * DD / 4; i += 256)
        ((float4*)ks)[i] = ((const float4*)vbase)[i];
    __syncthreads();

    // ctx[i,:] = sum_j at[i][j] * v[j,:] ; each thread owns 4 columns
    int c0 = tid * 4;
    for (int i = 0; i < 24; i++) {
        float4 acc = {0.f, 0.f, 0.f, 0.f};
        #pragma unroll
        for (int j = 0; j < 24; j++) {
            float a = at[i * 24 + j];
            float4 v4 = *(const float4*)&ks[j * DD + c0];
            acc.x += a * v4.x; acc.y += a * v4.y; acc.z += a * v4.z; acc.w += a * v4.w;
        }
        float* dst = (i < 12) ? ctx_r + ((size_t)bh * 12 + i) * DD
                              : ctx_t + ((size_t)bh * 12 + (i - 12)) * DD;
        *(float4*)&dst[c0] = acc;
    }
}

// ---------------------------------------------------------------------------
// Launch
// ---------------------------------------------------------------------------
extern "C" void kernel_launch(void* const* d_in, const int* in_sizes, int n_in,
                              void* d_out, int out_size) {
    const float* attn_rgb = (const float*)d_in[0];
    const float* attn_tir = (const float*)d_in[1];
    const float* pos_emb  = (const float*)d_in[2];
    const float* embed_w  = (const float*)d_in[3];
    const float* embed_b  = (const float*)d_in[4];
    const float* bn_w     = (const float*)d_in[5];
    const float* bn_b     = (const float*)d_in[6];
    const float* ln_w     = (const float*)d_in[7];
    const float* ln_b     = (const float*)d_in[8];
    const float* v_w      = (const float*)d_in[9];
    const float* v_b      = (const float*)d_in[10];
    const float* q_w      = (const float*)d_in[11];
    const float* q_b      = (const float*)d_in[12];
    const float* k_w      = (const float*)d_in[13];
    const float* k_b      = (const float*)d_in[14];
    const float* out_w    = (const float*)d_in[15];
    const float* out_b    = (const float*)d_in[16];
    float* out = (float*)d_out;

    float* base;
    cudaGetSymbolAddress((void**)&base, g_scratch);

    // Region map (aliased, stream-ordered reuse)
    float* emb_r = base + 0 * S1;
    float* emb_t = base + 1 * S1;
    float* lnin  = base + 2 * S1;   // dead after value GEMM
    float* qbr   = base + 2 * S1;   // reuses lnin region
    float* qbt   = base + 3 * S1;
    float* keyp  = base + 4 * S1;
    float* valp  = base + 6 * S1;
    float* ctr   = base + 0 * S1;   // reuses emb_r after key GEMM
    float* ctt   = base + 1 * S1;   // reuses emb_t after key GEMM

    cudaFuncSetAttribute(attn_kernel, cudaFuncAttributeMaxDynamicSharedMemorySize, (int)ATTN_SMEM);

    dim3 g1(DD / 128, M1 / 128);   // (8, 288)
    dim3 g2(DD / 128, M2 / 128);   // (8, 576)
    dim3 gbn(M1, 2);

    // 1. Embedding GEMMs
    gemm_tn<0><<<g1, 256>>>(attn_rgb, nullptr, embed_w, embed_b, emb_r);
    gemm_tn<0><<<g1, 256>>>(attn_tir, nullptr, embed_w, embed_b, emb_t);

    // 2. BatchNorm stats + apply (+ pos add), in place
    bn_zero_kernel<<<1, 32>>>();
    bn_stats_kernel<<<gbn, 256>>>(emb_r, emb_t);
    bn_finalize_kernel<<<1, 32>>>(bn_w, bn_b);
    bn_apply_kernel<<<gbn, 256>>>(emb_r, emb_t, pos_emb);

    // 3. LayerNorm of concat(raw rgb, raw tir) -> lnin, then value GEMM
    ln_kernel<<<M2, 256>>>(attn_rgb, attn_tir, ln_w, ln_b, lnin);
    gemm_tn<0><<<g2, 256>>>(lnin, nullptr, v_w, v_b, valp);

    // 4. k projection first (frees emb for ctx), then q projections
    //    (q writes over the lnin region, which is dead now)
    gemm_tn<1><<<g2, 256>>>(emb_r, emb_t, k_w, k_b, keyp);
    gemm_tn<0><<<g1, 256>>>(emb_r, nullptr, q_w, q_b, qbr);
    gemm_tn<0><<<g1, 256>>>(emb_t, nullptr, q_w, q_b, qbt);

    // 5. Attention (writes ctx into the emb region — emb fully consumed above)
    attn_kernel<<<BH, 256, ATTN_SMEM>>>(qbr, qbt, keyp, valp, ctr, ctt);

    // 6. Output projections straight into d_out (rgb first, then tir)
    gemm_tn<0><<<g1, 256>>>(ctr, nullptr, out_w, out_b, out);
    gemm_tn<0><<<g1, 256>>>(ctt, nullptr, out_w, out_b, out + (size_t)M1 * DD);
}

// round 5
// speedup vs baseline: 2.1056x; 2.1056x over previous
#include <cuda_runtime.h>
#include <cuda_bf16.h>
#include <cstdint>
#include <cstddef>

// Problem constants
#define BB   256
#define HN   12
#define N1   12
#define DD   1024
#define BH   (BB*HN)         // 3072
#define M1   (BH*N1)         // 36864
#define M2   (BH*2*N1)       // 73728

#define UU   ((size_t)M1 * DD)       // elements per M1-unit
#define WU   ((size_t)DD * DD)       // elements per weight matrix

// ---------------------------------------------------------------------------
// Static scratch
// bf16 arena (12 units):
//   0..1: ar hi/lo  -> later ctx_r hi/lo
//   2..3: at hi/lo  -> later ctx_t hi/lo
//   4..5: emb_r hi/lo   6..7: emb_t hi/lo
//   8..11: ln hi(2U) / lo(2U)
// fp32 arena (6 units): 0:emb_r->q_r 1:emb_t->q_t 2..3:key 4..5:val
// ---------------------------------------------------------------------------
__device__ __nv_bfloat16 g_bf[12 * UU];
__device__ __nv_bfloat16 g_wbf[10 * WU];   // ew h/l, vw h/l, qw h/l, kw h/l, ow h/l
__device__ float g_f32[6 * UU];

__device__ float g_bn_sum[2][12];
__device__ float g_bn_sq [2][12];
__device__ float g_bn_scale[2][12];
__device__ float g_bn_shift[2][12];

// ---------------------------------------------------------------------------
// Low-level helpers (non-'a' features only: cp.async, ldmatrix, mma.sync)
// ---------------------------------------------------------------------------
__device__ __forceinline__ uint32_t smem_to_u32(const void* p) {
    uint32_t a;
    asm("{ .reg .u64 t; cvta.to.shared.u64 t, %1; cvt.u32.u64 %0, t; }" : "=r"(a) : "l"(p));
    return a;
}
__device__ __forceinline__ void cp16(uint32_t dst, const void* src) {
    asm volatile("cp.async.cg.shared.global [%0], [%1], 16;\n" :: "r"(dst), "l"(src));
}
__device__ __forceinline__ void cp_commit() {
    asm volatile("cp.async.commit_group;\n" ::: "memory");
}
__device__ __forceinline__ void ldsm4(uint32_t addr, uint32_t& r0, uint32_t& r1,
                                      uint32_t& r2, uint32_t& r3) {
    asm volatile("ldmatrix.sync.aligned.m8n8.x4.shared.b16 {%0,%1,%2,%3}, [%4];"
        : "=r"(r0), "=r"(r1), "=r"(r2), "=r"(r3) : "r"(addr));
}
__device__ __forceinline__ void mma16816(float* c, const uint32_t* a, uint32_t b0, uint32_t b1) {
    asm volatile("mma.sync.aligned.m16n8k16.row.col.f32.bf16.bf16.f32 "
        "{%0,%1,%2,%3}, {%4,%5,%6,%7}, {%8,%9}, {%0,%1,%2,%3};"
        : "+f"(c[0]), "+f"(c[1]), "+f"(c[2]), "+f"(c[3])
        : "r"(a[0]), "r"(a[1]), "r"(a[2]), "r"(a[3]), "r"(b0), "r"(b1));
}

// smem tile layout: rows x 32 bf16 (64B rows); seg = 16B chunk index (0..3)
// swizzle: seg ^= (row>>1)&3  -> conflict-free ldmatrix phases
__device__ __forceinline__ uint32_t swz(int r, int s) {
    return (uint32_t)(r * 64 + ((s ^ ((r >> 1) & 3)) << 4));
}

// ---------------------------------------------------------------------------
// fp32 -> (bf16 hi, bf16 lo) split
// ---------------------------------------------------------------------------
__device__ __forceinline__ void split_bf16(float x, __nv_bfloat16& h, __nv_bfloat16& l) {
    h = __float2bfloat16(x);
    l = __float2bfloat16(x - __bfloat162float(h));
}

__global__ __launch_bounds__(256) void cvt_kernel(const float* __restrict__ x,
                                                  __nv_bfloat16* __restrict__ hi,
                                                  __nv_bfloat16* __restrict__ lo) {
    size_t idx = (size_t)blockIdx.x * 256 + threadIdx.x;   // one float4 per thread
    float4 v = ((const float4*)x)[idx];
    __nv_bfloat16 h0,h1,h2,h3,l0,l1,l2,l3;
    split_bf16(v.x,h0,l0); split_bf16(v.y,h1,l1); split_bf16(v.z,h2,l2); split_bf16(v.w,h3,l3);
    __nv_bfloat162* hp = (__nv_bfloat162*)hi;
    __nv_bfloat162* lp = (__nv_bfloat162*)lo;
    hp[idx*2]   = {h0,h1}; hp[idx*2+1] = {h2,h3};
    lp[idx*2]   = {l0,l1}; lp[idx*2+1] = {l2,l3};
}

// ---------------------------------------------------------------------------
// Tensor-core GEMM via mma.sync (bf16x3 split-precision, fp32 accum/out):
//   C[M,1024] = A[M,1024] @ W[1024,1024]^T + bias
// A,W given as bf16 hi (ptr) + lo (ptr + loD elements).
// Terms: Ah@Wh + Al@Wh + Ah@Wl.
// BM=128, BN=256, BK=32, 256 threads, 8 warps (2m x 4n), warp tile 64x64.
// 2-stage cp.async pipeline; stage = Ah(8K)+Al(8K)+Wh(16K)+Wl(16K) = 48KB.
// MODE 0: A row r -> A0h + r*1024. MODE 1: concat rows (j=r%24; <12 rgb else tir)
// ---------------------------------------------------------------------------
#define STAGE_BYTES 49152
#define GEMM_SMEM   (2 * STAGE_BYTES)

template<int MODE>
__global__ __launch_bounds__(256, 1) void tc_gemm(
    const __nv_bfloat16* __restrict__ A0h,
    const __nv_bfloat16* __restrict__ A1h,
    size_t loD,                              // elements: lo = hi + loD
    const __nv_bfloat16* __restrict__ Wh,    // lo at Wh + WU
    const float* __restrict__ bias,
    float* __restrict__ C)
{
    extern __shared__ char smem[];
    const uint32_t sb = smem_to_u32(smem);
    const int tid = threadIdx.x;
    const int bm = blockIdx.y * 128;
    const int bn = blockIdx.x * 256;

    // ---- loader setup ----
    const int lr = tid >> 1;            // A tile row 0..127 (2 threads/row)
    const int s0 = (tid & 1) * 2;       // seg pair 0-1 / 2-3
    int gr = bm + lr;
    const char* aP;
    if (MODE == 0) aP = (const char*)(A0h + (size_t)gr * DD);
    else {
        int bh = gr / 24, j = gr % 24;
        aP = (const char*)(((j < 12) ? A0h : A1h) + ((size_t)bh * 12 + (j % 12)) * DD);
    }
    const char* wP = (const char*)(Wh + (size_t)(bn + tid) * DD);   // W tile row = tid
    const size_t loB  = loD * 2;
    const size_t wLoB = WU * 2;

    const uint32_t aD0 = swz(lr, s0);
    const uint32_t aD1 = swz(lr, s0 + 1);
    uint32_t wD[4];
    #pragma unroll
    for (int j = 0; j < 4; j++) wD[j] = swz(tid, j);

    // ---- compute setup ----
    const int wid = tid >> 5, lane = tid & 31;
    const int wm = wid & 1, wn = wid >> 1;
    const int rowA = wm * 64 + (lane & 15);
    const int segA = lane >> 4;
    const int xA = (rowA >> 1) & 3;
    const uint32_t aRowOff = rowA * 64;
    uint32_t aCol[2];
    aCol[0] = (uint32_t)(((segA + 0) ^ xA) << 4);
    aCol[1] = (uint32_t)(((segA + 2) ^ xA) << 4);

    const int rowB = wn * 64 + (lane & 7) + ((lane >> 4) << 3);
    const int segB = (lane >> 3) & 1;
    const int xB = (rowB >> 1) & 3;
    const uint32_t bRowOff = rowB * 64;
    uint32_t bCol[2];
    bCol[0] = (uint32_t)(((segB + 0) ^ xB) << 4);
    bCol[1] = (uint32_t)(((segB + 2) ^ xB) << 4);

    float acc[4][8][4];
    #pragma unroll
    for (int i = 0; i < 4; i++)
        #pragma unroll
        for (int j = 0; j < 8; j++)
            #pragma unroll
            for (int t = 0; t < 4; t++) acc[i][j][t] = 0.f;

    auto load_stage = [&](int c, int st) {
        uint32_t B = sb + st * STAGE_BYTES;
        size_t off = (size_t)c * 64;     // 32 bf16 per chunk = 64B per row
        cp16(B + aD0,        aP + off + s0 * 16);
        cp16(B + aD1,        aP + off + s0 * 16 + 16);
        cp16(B + 8192 + aD0, aP + loB + off + s0 * 16);
        cp16(B + 8192 + aD1, aP + loB + off + s0 * 16 + 16);
        #pragma unroll
        for (int j = 0; j < 4; j++) {
            cp16(B + 16384 + wD[j], wP + off + j * 16);
            cp16(B + 32768 + wD[j], wP + wLoB + off + j * 16);
        }
        cp_commit();
    };

    auto do_mmas = [&](uint32_t a[4][4], uint32_t b[4][4]) {
        #pragma unroll
        for (int mi = 0; mi < 4; mi++)
            #pragma unroll
            for (int p = 0; p < 4; p++) {
                mma16816(acc[mi][2*p],   a[mi], b[p][0], b[p][1]);
                mma16816(acc[mi][2*p+1], a[mi], b[p][2], b[p][3]);
            }
    };

    auto compute_stage = [&](int st) {
        uint32_t base = sb + st * STAGE_BYTES;
        uint32_t aH = base + aRowOff;
        uint32_t aL = aH + 8192;
        uint32_t bH = base + 16384 + bRowOff;
        uint32_t bL = bH + 16384;
        #pragma unroll
        for (int k = 0; k < 2; k++) {
            uint32_t a[4][4], b[4][4];
            // term 1: Ah @ Wh
            #pragma unroll
            for (int p = 0; p < 4; p++)
                ldsm4(bH + p * 1024 + bCol[k], b[p][0], b[p][1], b[p][2], b[p][3]);
            #pragma unroll
            for (int mi = 0; mi < 4; mi++)
                ldsm4(aH + mi * 1024 + aCol[k], a[mi][0], a[mi][1], a[mi][2], a[mi][3]);
            do_mmas(a, b);
            // term 2: Al @ Wh
            #pragma unroll
            for (int mi = 0; mi < 4; mi++)
                ldsm4(aL + mi * 1024 + aCol[k], a[mi][0], a[mi][1], a[mi][2], a[mi][3]);
            do_mmas(a, b);
            // term 3: Ah @ Wl
            #pragma unroll
            for (int p = 0; p < 4; p++)
                ldsm4(bL + p * 1024 + bCol[k], b[p][0], b[p][1], b[p][2], b[p][3]);
            #pragma unroll
            for (int mi = 0; mi < 4; mi++)
                ldsm4(aH + mi * 1024 + aCol[k], a[mi][0], a[mi][1], a[mi][2], a[mi][3]);
            do_mmas(a, b);
        }
    };

    // ---- pipeline over 32 K-chunks ----
    load_stage(0, 0);
    #pragma unroll 1
    for (int c = 0; c < 32; c++) {
        int st = c & 1;
        if (c + 1 < 32) {
            load_stage(c + 1, st ^ 1);
            asm volatile("cp.async.wait_group 1;" ::: "memory");
        } else {
            asm volatile("cp.async.wait_group 0;" ::: "memory");
        }
        __syncthreads();
        compute_stage(st);
        __syncthreads();
    }

    // ---- epilogue: direct global stores with bias ----
    const int r0   = bm + wm * 64 + (lane >> 2);
    const int col0 = bn + wn * 64 + (lane & 3) * 2;
    #pragma unroll
    for (int nf = 0; nf < 8; nf++) {
        int col = col0 + nf * 8;
        float bx = bias[col], by = bias[col + 1];
        #pragma unroll
        for (int mi = 0; mi < 4; mi++) {
            float* p0 = C + (size_t)(r0 + mi * 16) * DD + col;
            float2 v0 = { acc[mi][nf][0] + bx, acc[mi][nf][1] + by };
            float2 v1 = { acc[mi][nf][2] + bx, acc[mi][nf][3] + by };
            *(float2*)p0 = v0;
            *(float2*)(p0 + 8 * DD) = v1;
        }
    }
}

// ---------------------------------------------------------------------------
// BatchNorm
// ---------------------------------------------------------------------------
__global__ void bn_zero_kernel() {
    int t = threadIdx.x;
    if (t < 24) { ((float*)g_bn_sum)[t] = 0.f; ((float*)g_bn_sq)[t] = 0.f; }
}

__global__ __launch_bounds__(256) void bn_stats_kernel(const float* __restrict__ x0,
                                                       const float* __restrict__ x1) {
    int row  = blockIdx.x;
    int sidx = blockIdx.y;
    int tid  = threadIdx.x;
    const float* x = sidx ? x1 : x0;
    float4 v = ((const float4*)(x + (size_t)row * DD))[tid];
    float s = v.x + v.y + v.z + v.w;
    float q = v.x*v.x + v.y*v.y + v.z*v.z + v.w*v.w;
    #pragma unroll
    for (int o = 16; o > 0; o >>= 1) {
        s += __shfl_xor_sync(~0u, s, o);
        q += __shfl_xor_sync(~0u, q, o);
    }
    __shared__ float ss[8], qq[8];
    if ((tid & 31) == 0) { ss[tid >> 5] = s; qq[tid >> 5] = q; }
    __syncthreads();
    if (tid == 0) {
        float S = 0.f, Q = 0.f;
        #pragma unroll
        for (int w = 0; w < 8; w++) { S += ss[w]; Q += qq[w]; }
        atomicAdd(&g_bn_sum[sidx][row % 12], S);
        atomicAdd(&g_bn_sq [sidx][row % 12], Q);
    }
}

__global__ void bn_finalize_kernel(const float* __restrict__ bn_w, const float* __restrict__ bn_b) {
    int t = threadIdx.x;
    if (t < 24) {
        int s = t / 12, c = t % 12;
        const float CNT = 3072.0f * 1024.0f;
        float mean = g_bn_sum[s][c] / CNT;
        float var  = g_bn_sq [s][c] / CNT - mean * mean;
        float rstd = rsqrtf(var + 1e-5f);
        float sc   = rstd * bn_w[c];
        g_bn_scale[s][c] = sc;
        g_bn_shift[s][c] = bn_b[c] - mean * sc;
    }
}

// y = x*scale + shift + pos  -> bf16 hi/lo (lo = hi + UU)
__global__ __launch_bounds__(256) void bn_apply_cvt_kernel(const float* __restrict__ x0,
                                                           const float* __restrict__ x1,
                                                           const float* __restrict__ pos,
                                                           __nv_bfloat16* __restrict__ h0,
                                                           __nv_bfloat16* __restrict__ h1) {
    int row  = blockIdx.x;
    int sidx = blockIdx.y;
    int tid  = threadIdx.x;
    const float* x = sidx ? x1 : x0;
    __nv_bfloat16* hp = sidx ? h1 : h0;
    int c = row % 12;
    int b = row / 144;
    float sc = g_bn_scale[sidx][c], sh = g_bn_shift[sidx][c];
    float4 p = ((const float4*)(pos + ((size_t)(b * 12 + c)) * DD))[tid];
    float4 v = ((const float4*)(x + (size_t)row * DD))[tid];
    float y0 = v.x * sc + sh + p.x;
    float y1 = v.y * sc + sh + p.y;
    float y2 = v.z * sc + sh + p.z;
    float y3 = v.w * sc + sh + p.w;
    __nv_bfloat16 a0,a1,a2,a3,l0,l1,l2,l3;
    split_bf16(y0,a0,l0); split_bf16(y1,a1,l1); split_bf16(y2,a2,l2); split_bf16(y3,a3,l3);
    size_t base = (size_t)row * DD + tid * 4;
    __nv_bfloat162* hh = (__nv_bfloat162*)(hp + base);
    __nv_bfloat162* ll = (__nv_bfloat162*)(hp + UU + base);
    hh[0] = {a0,a1}; hh[1] = {a2,a3};
    ll[0] = {l0,l1}; ll[1] = {l2,l3};
}

// ---------------------------------------------------------------------------
// LayerNorm of concat(ar, at) -> bf16 hi/lo (lo at hi + 2U)
// ---------------------------------------------------------------------------
__global__ __launch_bounds__(256) void ln_cvt_kernel(const float* __restrict__ ar,
                                                     const float* __restrict__ at,
                                                     const float* __restrict__ lnw,
                                                     const float* __restrict__ lnb,
                                                     __nv_bfloat16* __restrict__ hi) {
    int row = blockIdx.x;
    int tid = threadIdx.x;
    int bh = row / 24, j = row % 24;
    const float* src = (j < 12) ? ar + ((size_t)bh * 12 + j) * DD
                                : at + ((size_t)bh * 12 + (j - 12)) * DD;
    float4 v = ((const float4*)src)[tid];
    float s = v.x + v.y + v.z + v.w;
    float q = v.x*v.x + v.y*v.y + v.z*v.z + v.w*v.w;
    #pragma unroll
    for (int o = 16; o > 0; o >>= 1) {
        s += __shfl_xor_sync(~0u, s, o);
        q += __shfl_xor_sync(~0u, q, o);
    }
    __shared__ float ss[8], qq[8], mom[2];
    if ((tid & 31) == 0) { ss[tid >> 5] = s; qq[tid >> 5] = q; }
    __syncthreads();
    if (tid == 0) {
        float S = 0.f, Q = 0.f;
        #pragma unroll
        for (int w = 0; w < 8; w++) { S += ss[w]; Q += qq[w]; }
        float mean = S / 1024.0f;
        float var  = Q / 1024.0f - mean * mean;
        mom[0] = mean;
        mom[1] = rsqrtf(var + 1e-5f);
    }
    __syncthreads();
    float mean = mom[0], rstd = mom[1];
    float4 w = ((const float4*)lnw)[tid];
    float4 bb = ((const float4*)lnb)[tid];
    float y0 = (v.x - mean) * rstd * w.x + bb.x;
    float y1 = (v.y - mean) * rstd * w.y + bb.y;
    float y2 = (v.z - mean) * rstd * w.z + bb.z;
    float y3 = (v.w - mean) * rstd * w.w + bb.w;
    __nv_bfloat16 a0,a1,a2,a3,l0,l1,l2,l3;
    split_bf16(y0,a0,l0); split_bf16(y1,a1,l1); split_bf16(y2,a2,l2); split_bf16(y3,a3,l3);
    size_t base = (size_t)row * DD + tid * 4;
    __nv_bfloat162* hh = (__nv_bfloat162*)(hi + base);
    __nv_bfloat162* ll = (__nv_bfloat162*)(hi + 2*UU + base);
    hh[0] = {a0,a1}; hh[1] = {a2,a3};
    ll[0] = {l0,l1}; ll[1] = {l2,l3};
}

// ---------------------------------------------------------------------------
// Fused attention: fp32 q/k/v in, bf16 hi/lo ctx out (lo at hi + UU)
// ---------------------------------------------------------------------------
#define ATTN_SMEM ((24*1024 + 24*24) * sizeof(float))

__global__ __launch_bounds__(256) void attn_kernel(
    const float* __restrict__ qr, const float* __restrict__ qt,
    const float* __restrict__ key, const float* __restrict__ val,
    __nv_bfloat16* __restrict__ ch_r, __nv_bfloat16* __restrict__ ch_t) {
    extern __shared__ float sm[];
    float* ks = sm;
    float* at = sm + 24 * 1024;

    int bh  = blockIdx.x;
    int tid = threadIdx.x;
    int warp = tid >> 5, lane = tid & 31;

    const float* kbase = key + (size_t)bh * 24 * DD;
    for (int i = tid; i < 24 * DD / 4; i += 256)
        ((float4*)ks)[i] = ((const float4*)kbase)[i];
    __syncthreads();

    for (int qi = warp * 3; qi < warp * 3 + 3; qi++) {
        const float* qrow = (qi < 12) ? qr + ((size_t)bh * 12 + qi) * DD
                                      : qt + ((size_t)bh * 12 + (qi - 12)) * DD;
        float qv[32];
        #pragma unroll
        for (int t = 0; t < 32; t++) qv[t] = qrow[t * 32 + lane];
        for (int j = 0; j < 24; j++) {
            float s = 0.f;
            #pragma unroll
            for (int t = 0; t < 32; t++) s += qv[t] * ks[j * DD + t * 32 + lane];
            #pragma unroll
            for (int o = 16; o > 0; o >>= 1) s += __shfl_xor_sync(~0u, s, o);
            if (lane == 0) at[qi * 24 + j] = s * 0.03125f;
        }
    }
    __syncthreads();

    for (int qi = warp * 3; qi < warp * 3 + 3; qi++) {
        float v = (lane < 24) ? at[qi * 24 + lane] : -3.0e38f;
        float m = v;
        #pragma unroll
        for (int o = 16; o > 0; o >>= 1) m = fmaxf(m, __shfl_xor_sync(~0u, m, o));
        float e = (lane < 24) ? expf(v - m) : 0.f;
        float s = e;
        #pragma unroll
        for (int o = 16; o > 0; o >>= 1) s += __shfl_xor_sync(~0u, s, o);
        if (lane < 24) at[qi * 24 + lane] = e / s;
    }
    __syncthreads();

    const float* vbase = val + (size_t)bh * 24 * DD;
    for (int i = tid; i < 24 * DD / 4; i += 256)
        ((float4*)ks)[i] = ((const float4*)vbase)[i];
    __syncthreads();

    int c0 = tid * 4;
    for (int i = 0; i < 24; i++) {
        float4 acc = {0.f, 0.f, 0.f, 0.f};
        #pragma unroll
        for (int j = 0; j < 24; j++) {
            float a = at[i * 24 + j];
            float4 v4 = *(const float4*)&ks[j * DD + c0];
            acc.x += a * v4.x; acc.y += a * v4.y; acc.z += a * v4.z; acc.w += a * v4.w;
        }
        __nv_bfloat16* dsth = (i < 12) ? ch_r : ch_t;
        size_t base = ((size_t)bh * 12 + (i % 12)) * DD + c0;
        __nv_bfloat16 a0,a1,a2,a3,l0,l1,l2,l3;
        split_bf16(acc.x,a0,l0); split_bf16(acc.y,a1,l1);
        split_bf16(acc.z,a2,l2); split_bf16(acc.w,a3,l3);
        __nv_bfloat162* hh = (__nv_bfloat162*)(dsth + base);
        __nv_bfloat162* ll = (__nv_bfloat162*)(dsth + UU + base);
        hh[0] = {a0,a1}; hh[1] = {a2,a3};
        ll[0] = {l0,l1}; ll[1] = {l2,l3};
    }
}

// ---------------------------------------------------------------------------
// Launch
// ---------------------------------------------------------------------------
extern "C" void kernel_launch(void* const* d_in, const int* in_sizes, int n_in,
                              void* d_out, int out_size) {
    const float* attn_rgb = (const float*)d_in[0];
    const float* attn_tir = (const float*)d_in[1];
    const float* pos_emb  = (const float*)d_in[2];
    const float* embed_w  = (const float*)d_in[3];
    const float* embed_b  = (const float*)d_in[4];
    const float* bn_w     = (const float*)d_in[5];
    const float* bn_b     = (const float*)d_in[6];
    const float* ln_w     = (const float*)d_in[7];
    const float* ln_b     = (const float*)d_in[8];
    const float* v_w      = (const float*)d_in[9];
    const float* v_b      = (const float*)d_in[10];
    const float* q_w      = (const float*)d_in[11];
    const float* q_b      = (const float*)d_in[12];
    const float* k_w      = (const float*)d_in[13];
    const float* k_b      = (const float*)d_in[14];
    const float* out_w    = (const float*)d_in[15];
    const float* out_b    = (const float*)d_in[16];
    float* out = (float*)d_out;

    __nv_bfloat16 *bf, *wbf;
    float* f32;
    cudaGetSymbolAddress((void**)&bf,  g_bf);
    cudaGetSymbolAddress((void**)&wbf, g_wbf);
    cudaGetSymbolAddress((void**)&f32, g_f32);

    // bf16 arena regions
    __nv_bfloat16* arh    = bf + 0*UU;   // -> ctx_r later
    __nv_bfloat16* ath    = bf + 2*UU;   // -> ctx_t later
    __nv_bfloat16* embh_r = bf + 4*UU;
    __nv_bfloat16* embh_t = bf + 6*UU;
    __nv_bfloat16* lnh    = bf + 8*UU;   // 2U long, lo at +2U
    __nv_bfloat16* ctxh_r = bf + 0*UU;
    __nv_bfloat16* ctxh_t = bf + 2*UU;
    // fp32 arena
    float* emb_r = f32 + 0*UU;   // -> q_r later
    float* emb_t = f32 + 1*UU;   // -> q_t later
    float* keyp  = f32 + 2*UU;
    float* valp  = f32 + 4*UU;
    float* q_r   = f32 + 0*UU;
    float* q_t   = f32 + 1*UU;

    cudaFuncSetAttribute(tc_gemm<0>, cudaFuncAttributeMaxDynamicSharedMemorySize, GEMM_SMEM);
    cudaFuncSetAttribute(tc_gemm<1>, cudaFuncAttributeMaxDynamicSharedMemorySize, GEMM_SMEM);
    cudaFuncSetAttribute(attn_kernel, cudaFuncAttributeMaxDynamicSharedMemorySize, (int)ATTN_SMEM);

    dim3 g1(4, M1 / 128);     // (4, 288)
    dim3 g2(4, M2 / 128);     // (4, 576)
    dim3 gbn(M1, 2);

    // 0. Splits: inputs + weights -> bf16 hi/lo
    cvt_kernel<<<(int)(UU/1024), 256>>>(attn_rgb, arh, arh + UU);
    cvt_kernel<<<(int)(UU/1024), 256>>>(attn_tir, ath, ath + UU);
    cvt_kernel<<<(int)(WU/1024), 256>>>(embed_w, wbf + 0*WU, wbf + 1*WU);
    cvt_kernel<<<(int)(WU/1024), 256>>>(v_w,     wbf + 2*WU, wbf + 3*WU);
    cvt_kernel<<<(int)(WU/1024), 256>>>(q_w,     wbf + 4*WU, wbf + 5*WU);
    cvt_kernel<<<(int)(WU/1024), 256>>>(k_w,     wbf + 6*WU, wbf + 7*WU);
    cvt_kernel<<<(int)(WU/1024), 256>>>(out_w,   wbf + 8*WU, wbf + 9*WU);

    // 1. Embedding GEMMs -> fp32
    tc_gemm<0><<<g1, 256, GEMM_SMEM>>>(arh, nullptr, UU, wbf + 0*WU, embed_b, emb_r);
    tc_gemm<0><<<g1, 256, GEMM_SMEM>>>(ath, nullptr, UU, wbf + 0*WU, embed_b, emb_t);

    // 2. BatchNorm stats + fused apply/pos/split -> emb bf16 hi/lo
    bn_zero_kernel<<<1, 32>>>();
    bn_stats_kernel<<<gbn, 256>>>(emb_r, emb_t);
    bn_finalize_kernel<<<1, 32>>>(bn_w, bn_b);
    bn_apply_cvt_kernel<<<gbn, 256>>>(emb_r, emb_t, pos_emb, embh_r, embh_t);

    // 3. LayerNorm (fused split) -> value GEMM
    ln_cvt_kernel<<<M2, 256>>>(attn_rgb, attn_tir, ln_w, ln_b, lnh);
    tc_gemm<0><<<g2, 256, GEMM_SMEM>>>(lnh, nullptr, 2*UU, wbf + 2*WU, v_b, valp);

    // 4. key (concat rows) then q projections (q overwrites dead emb fp32)
    tc_gemm<1><<<g2, 256, GEMM_SMEM>>>(embh_r, embh_t, UU, wbf + 6*WU, k_b, keyp);
    tc_gemm<0><<<g1, 256, GEMM_SMEM>>>(embh_r, nullptr, UU, wbf + 4*WU, q_b, q_r);
    tc_gemm<0><<<g1, 256, GEMM_SMEM>>>(embh_t, nullptr, UU, wbf + 4*WU, q_b, q_t);

    // 5. Attention -> ctx bf16 hi/lo (overwrites dead ar/at region)
    attn_kernel<<<BH, 256, ATTN_SMEM>>>(q_r, q_t, keyp, valp, ctxh_r, ctxh_t);

    // 6. Output projections -> d_out fp32
    tc_gemm<0><<<g1, 256, GEMM_SMEM>>>(ctxh_r, nullptr, UU, wbf + 8*WU, out_b, out);
    tc_gemm<0><<<g1, 256, GEMM_SMEM>>>(ctxh_t, nullptr, UU, wbf + 8*WU, out_b, out + UU);
}

// round 6
// speedup vs baseline: 3.0522x; 1.4495x over previous
#include <cuda_runtime.h>
#include <cuda_bf16.h>
#include <cstdint>
#include <cstddef>

// Problem constants
#define BB   256
#define HN   12
#define N1   12
#define DD   1024
#define BH   (BB*HN)         // 3072
#define M1   (BH*N1)         // 36864
#define M2   (BH*2*N1)       // 73728

#define UU   ((size_t)M1 * DD)       // elements per M1-unit
#define WU   ((size_t)DD * DD)       // elements per weight matrix

// ---------------------------------------------------------------------------
// Static scratch
// bf16 arena (8 units):
//   0..3: ar h/l, at h/l   -> later ln hi(2U at 0..1) / lo(2U at 2..3)
//   4..7: emb_r h/l, emb_t h/l
// bf16 weight arena (14 WU): ew h/l | qwT h/l | kwT h/l | vwT h/l | ow h/l | GT h/l | W2 h/l
// fp32 arena (4 units): 0:emb_r->qg_r 1:emb_t->qg_t 2..3:value'
// fp32 weight scratch (5 WU): qwT kwT vwT GT W2
// ---------------------------------------------------------------------------
__device__ __nv_bfloat16 g_bf[8 * UU];
__device__ __nv_bfloat16 g_wbf[14 * WU];
__device__ float g_f32[4 * UU];
__device__ float g_wf32[5 * WU];

__device__ float g_bn_sum[2][12];
__device__ float g_bn_sq [2][12];
__device__ float g_bn_scale[2][12];
__device__ float g_bn_shift[2][12];

__device__ float g_u[DD];
__device__ float g_v[DD];
__device__ float g_b2[DD];
__device__ float g_misc[4];
__device__ float g_zeros[DD];        // zero-initialized (static storage)
__device__ float g_dq[2 * M1];
__device__ float g_dk[2 * M1];

// ---------------------------------------------------------------------------
// Low-level helpers (non-'a' features only: cp.async, ldmatrix, mma.sync)
// ---------------------------------------------------------------------------
__device__ __forceinline__ uint32_t smem_to_u32(const void* p) {
    uint32_t a;
    asm("{ .reg .u64 t; cvta.to.shared.u64 t, %1; cvt.u32.u64 %0, t; }" : "=r"(a) : "l"(p));
    return a;
}
__device__ __forceinline__ void cp16(uint32_t dst, const void* src) {
    asm volatile("cp.async.cg.shared.global [%0], [%1], 16;\n" :: "r"(dst), "l"(src));
}
__device__ __forceinline__ void cp_commit() {
    asm volatile("cp.async.commit_group;\n" ::: "memory");
}
__device__ __forceinline__ void ldsm4(uint32_t addr, uint32_t& r0, uint32_t& r1,
                                      uint32_t& r2, uint32_t& r3) {
    asm volatile("ldmatrix.sync.aligned.m8n8.x4.shared.b16 {%0,%1,%2,%3}, [%4];"
        : "=r"(r0), "=r"(r1), "=r"(r2), "=r"(r3) : "r"(addr));
}
__device__ __forceinline__ void mma16816(float* c, const uint32_t* a, uint32_t b0, uint32_t b1) {
    asm volatile("mma.sync.aligned.m16n8k16.row.col.f32.bf16.bf16.f32 "
        "{%0,%1,%2,%3}, {%4,%5,%6,%7}, {%8,%9}, {%0,%1,%2,%3};"
        : "+f"(c[0]), "+f"(c[1]), "+f"(c[2]), "+f"(c[3])
        : "r"(a[0]), "r"(a[1]), "r"(a[2]), "r"(a[3]), "r"(b0), "r"(b1));
}

// smem tile layout: rows x 32 bf16 (64B rows); seg = 16B chunk index (0..3)
__device__ __forceinline__ uint32_t swz(int r, int s) {
    return (uint32_t)(r * 64 + ((s ^ ((r >> 1) & 3)) << 4));
}

// ---------------------------------------------------------------------------
// fp32 -> (bf16 hi, bf16 lo) split
// ---------------------------------------------------------------------------
__device__ __forceinline__ void split_bf16(float x, __nv_bfloat16& h, __nv_bfloat16& l) {
    h = __float2bfloat16(x);
    l = __float2bfloat16(x - __bfloat162float(h));
}

__global__ __launch_bounds__(256) void cvt_kernel(const float* __restrict__ x,
                                                  __nv_bfloat16* __restrict__ hi,
                                                  __nv_bfloat16* __restrict__ lo) {
    size_t idx = (size_t)blockIdx.x * 256 + threadIdx.x;
    float4 v = ((const float4*)x)[idx];
    __nv_bfloat16 h0,h1,h2,h3,l0,l1,l2,l3;
    split_bf16(v.x,h0,l0); split_bf16(v.y,h1,l1); split_bf16(v.z,h2,l2); split_bf16(v.w,h3,l3);
    __nv_bfloat162* hp = (__nv_bfloat162*)hi;
    __nv_bfloat162* lp = (__nv_bfloat162*)lo;
    hp[idx*2]   = {h0,h1}; hp[idx*2+1] = {h2,h3};
    lp[idx*2]   = {l0,l1}; lp[idx*2+1] = {l2,l3};
}

// ---------------------------------------------------------------------------
// 1024x1024 fp32 transpose
// ---------------------------------------------------------------------------
__global__ void transpose_kernel(const float* __restrict__ src, float* __restrict__ dst) {
    __shared__ float t[32][33];
    int x = blockIdx.x * 32 + threadIdx.x;
    int y = blockIdx.y * 32 + threadIdx.y;
    #pragma unroll
    for (int r = 0; r < 4; r++)
        t[threadIdx.y + r * 8][threadIdx.x] = src[(size_t)(y + r * 8) * DD + x];
    __syncthreads();
    int x2 = blockIdx.y * 32 + threadIdx.x;
    int y2 = blockIdx.x * 32 + threadIdx.y;
    #pragma unroll
    for (int r = 0; r < 4; r++)
        dst[(size_t)(y2 + r * 8) * DD + x2] = t[threadIdx.x][threadIdx.y + r * 8];
}

// ---------------------------------------------------------------------------
// Tensor-core GEMM via mma.sync (bf16x3 split-precision, fp32 accum/out):
//   C[M,1024] = A[M,1024] @ W[1024,1024]^T + bias
// A hi (ptr) + lo (ptr + loD elements). W hi (ptr) + lo (ptr + WU).
// Terms: Ah@Wh + Al@Wh + Ah@Wl.
// BM=128, BN=256, BK=32, 256 threads, 8 warps (2m x 4n), warp tile 64x64.
// ---------------------------------------------------------------------------
#define STAGE_BYTES 49152
#define GEMM_SMEM   (2 * STAGE_BYTES)

__global__ __launch_bounds__(256, 1) void tc_gemm(
    const __nv_bfloat16* __restrict__ A0h,
    size_t loD,
    const __nv_bfloat16* __restrict__ Wh,
    const float* __restrict__ bias,
    float* __restrict__ C)
{
    extern __shared__ char smem[];
    const uint32_t sb = smem_to_u32(smem);
    const int tid = threadIdx.x;
    const int bm = blockIdx.y * 128;
    const int bn = blockIdx.x * 256;

    // ---- loader setup ----
    const int lr = tid >> 1;
    const int s0 = (tid & 1) * 2;
    const char* aP = (const char*)(A0h + (size_t)(bm + lr) * DD);
    const char* wP = (const char*)(Wh + (size_t)(bn + tid) * DD);
    const size_t loB  = loD * 2;
    const size_t wLoB = WU * 2;

    const uint32_t aD0 = swz(lr, s0);
    const uint32_t aD1 = swz(lr, s0 + 1);
    uint32_t wD[4];
    #pragma unroll
    for (int j = 0; j < 4; j++) wD[j] = swz(tid, j);

    // ---- compute setup ----
    const int wid = tid >> 5, lane = tid & 31;
    const int wm = wid & 1, wn = wid >> 1;
    const int rowA = wm * 64 + (lane & 15);
    const int segA = lane >> 4;
    const int xA = (rowA >> 1) & 3;
    const uint32_t aRowOff = rowA * 64;
    uint32_t aCol[2];
    aCol[0] = (uint32_t)(((segA + 0) ^ xA) << 4);
    aCol[1] = (uint32_t)(((segA + 2) ^ xA) << 4);

    const int rowB = wn * 64 + (lane & 7) + ((lane >> 4) << 3);
    const int segB = (lane >> 3) & 1;
    const int xB = (rowB >> 1) & 3;
    const uint32_t bRowOff = rowB * 64;
    uint32_t bCol[2];
    bCol[0] = (uint32_t)(((segB + 0) ^ xB) << 4);
    bCol[1] = (uint32_t)(((segB + 2) ^ xB) << 4);

    float acc[4][8][4];
    #pragma unroll
    for (int i = 0; i < 4; i++)
        #pragma unroll
        for (int j = 0; j < 8; j++)
            #pragma unroll
            for (int t = 0; t < 4; t++) acc[i][j][t] = 0.f;

    auto load_stage = [&](int c, int st) {
        uint32_t B = sb + st * STAGE_BYTES;
        size_t off = (size_t)c * 64;
        cp16(B + aD0,        aP + off + s0 * 16);
        cp16(B + aD1,        aP + off + s0 * 16 + 16);
        cp16(B + 8192 + aD0, aP + loB + off + s0 * 16);
        cp16(B + 8192 + aD1, aP + loB + off + s0 * 16 + 16);
        #pragma unroll
        for (int j = 0; j < 4; j++) {
            cp16(B + 16384 + wD[j], wP + off + j * 16);
            cp16(B + 32768 + wD[j], wP + wLoB + off + j * 16);
        }
        cp_commit();
    };

    auto do_mmas = [&](uint32_t a[4][4], uint32_t b[4][4]) {
        #pragma unroll
        for (int mi = 0; mi < 4; mi++)
            #pragma unroll
            for (int p = 0; p < 4; p++) {
                mma16816(acc[mi][2*p],   a[mi], b[p][0], b[p][1]);
                mma16816(acc[mi][2*p+1], a[mi], b[p][2], b[p][3]);
            }
    };

    auto compute_stage = [&](int st) {
        uint32_t base = sb + st * STAGE_BYTES;
        uint32_t aH = base + aRowOff;
        uint32_t aL = aH + 8192;
        uint32_t bH = base + 16384 + bRowOff;
        uint32_t bL = bH + 16384;
        #pragma unroll
        for (int k = 0; k < 2; k++) {
            uint32_t a[4][4], b[4][4];
            #pragma unroll
            for (int p = 0; p < 4; p++)
                ldsm4(bH + p * 1024 + bCol[k], b[p][0], b[p][1], b[p][2], b[p][3]);
            #pragma unroll
            for (int mi = 0; mi < 4; mi++)
                ldsm4(aH + mi * 1024 + aCol[k], a[mi][0], a[mi][1], a[mi][2], a[mi][3]);
            do_mmas(a, b);
            #pragma unroll
            for (int mi = 0; mi < 4; mi++)
                ldsm4(aL + mi * 1024 + aCol[k], a[mi][0], a[mi][1], a[mi][2], a[mi][3]);
            do_mmas(a, b);
            #pragma unroll
            for (int p = 0; p < 4; p++)
                ldsm4(bL + p * 1024 + bCol[k], b[p][0], b[p][1], b[p][2], b[p][3]);
            #pragma unroll
            for (int mi = 0; mi < 4; mi++)
                ldsm4(aH + mi * 1024 + aCol[k], a[mi][0], a[mi][1], a[mi][2], a[mi][3]);
            do_mmas(a, b);
        }
    };

    load_stage(0, 0);
    #pragma unroll 1
    for (int c = 0; c < 32; c++) {
        int st = c & 1;
        if (c + 1 < 32) {
            load_stage(c + 1, st ^ 1);
            asm volatile("cp.async.wait_group 1;" ::: "memory");
        } else {
            asm volatile("cp.async.wait_group 0;" ::: "memory");
        }
        __syncthreads();
        compute_stage(st);
        __syncthreads();
    }

    const int r0   = bm + wm * 64 + (lane >> 2);
    const int col0 = bn + wn * 64 + (lane & 3) * 2;
    #pragma unroll
    for (int nf = 0; nf < 8; nf++) {
        int col = col0 + nf * 8;
        float bx = bias[col], by = bias[col + 1];
        #pragma unroll
        for (int mi = 0; mi < 4; mi++) {
            float* p0 = C + (size_t)(r0 + mi * 16) * DD + col;
            float2 v0 = { acc[mi][nf][0] + bx, acc[mi][nf][1] + by };
            float2 v1 = { acc[mi][nf][2] + bx, acc[mi][nf][3] + by };
            *(float2*)p0 = v0;
            *(float2*)(p0 + 8 * DD) = v1;
        }
    }
}

// ---------------------------------------------------------------------------
// Small GEMV-ish kernels for bias-term algebra
// u[d] = sum_c qw[c,d]*kb[c];  v[d] = sum_c kw[c,d]*qb[c];  misc[0] = qb.kb
// ---------------------------------------------------------------------------
__global__ __launch_bounds__(256) void uv_kernel(const float* __restrict__ qw,
                                                 const float* __restrict__ kw,
                                                 const float* __restrict__ qb,
                                                 const float* __restrict__ kb) {
    if (blockIdx.x < 4) {
        int d = blockIdx.x * 256 + threadIdx.x;
        float su = 0.f, sv = 0.f;
        for (int c = 0; c < DD; c++) {
            su += qw[(size_t)c * DD + d] * kb[c];
            sv += kw[(size_t)c * DD + d] * qb[c];
        }
        g_u[d] = su;
        g_v[d] = sv;
    } else {
        int tid = threadIdx.x;
        float s = qb[tid]*kb[tid] + qb[tid+256]*kb[tid+256]
                + qb[tid+512]*kb[tid+512] + qb[tid+768]*kb[tid+768];
        #pragma unroll
        for (int o = 16; o > 0; o >>= 1) s += __shfl_xor_sync(~0u, s, o);
        __shared__ float ss[8];
        if ((tid & 31) == 0) ss[tid >> 5] = s;
        __syncthreads();
        if (tid == 0) {
            float S = 0.f;
            #pragma unroll
            for (int w = 0; w < 8; w++) S += ss[w];
            g_misc[0] = S;
        }
    }
}

// b2[n] = sum_c ow[n,c] * vb[c]   (warp per row)
__global__ __launch_bounds__(256) void bias2_kernel(const float* __restrict__ ow,
                                                    const float* __restrict__ vb) {
    int wid = threadIdx.x >> 5, lane = threadIdx.x & 31;
    int row = blockIdx.x * 8 + wid;
    const float* r = ow + (size_t)row * DD;
    float s = 0.f;
    for (int c = lane; c < DD; c += 32) s += r[c] * vb[c];
    #pragma unroll
    for (int o = 16; o > 0; o >>= 1) s += __shfl_xor_sync(~0u, s, o);
    if (lane == 0) g_b2[row] = s;
}

// dq[s*M1+row] = dot(x_row, u); dk[s*M1+row] = dot(x_row, v); x = emb hi+lo
__global__ __launch_bounds__(256) void dqdk_kernel(const __nv_bfloat16* __restrict__ h0,
                                                   const __nv_bfloat16* __restrict__ h1) {
    int row = blockIdx.x, sidx = blockIdx.y, tid = threadIdx.x;
    const __nv_bfloat16* h = sidx ? h1 : h0;
    size_t base = (size_t)row * DD + tid * 4;
    const __nv_bfloat162* hh = (const __nv_bfloat162*)(h + base);
    const __nv_bfloat162* ll = (const __nv_bfloat162*)(h + UU + base);
    __nv_bfloat162 a0 = hh[0], a1 = hh[1], b0 = ll[0], b1 = ll[1];
    float x0 = __bfloat162float(a0.x) + __bfloat162float(b0.x);
    float x1 = __bfloat162float(a0.y) + __bfloat162float(b0.y);
    float x2 = __bfloat162float(a1.x) + __bfloat162float(b1.x);
    float x3 = __bfloat162float(a1.y) + __bfloat162float(b1.y);
    float4 u4 = ((const float4*)g_u)[tid];
    float4 v4 = ((const float4*)g_v)[tid];
    float su = x0*u4.x + x1*u4.y + x2*u4.z + x3*u4.w;
    float sv = x0*v4.x + x1*v4.y + x2*v4.z + x3*v4.w;
    #pragma unroll
    for (int o = 16; o > 0; o >>= 1) {
        su += __shfl_xor_sync(~0u, su, o);
        sv += __shfl_xor_sync(~0u, sv, o);
    }
    __shared__ float ssu[8], ssv[8];
    if ((tid & 31) == 0) { ssu[tid >> 5] = su; ssv[tid >> 5] = sv; }
    __syncthreads();
    if (tid == 0) {
        float SU = 0.f, SV = 0.f;
        #pragma unroll
        for (int w = 0; w < 8; w++) { SU += ssu[w]; SV += ssv[w]; }
        g_dq[sidx * M1 + row] = SU;
        g_dk[sidx * M1 + row] = SV;
    }
}

// ---------------------------------------------------------------------------
// BatchNorm
// ---------------------------------------------------------------------------
__global__ void bn_zero_kernel() {
    int t = threadIdx.x;
    if (t < 24) { ((float*)g_bn_sum)[t] = 0.f; ((float*)g_bn_sq)[t] = 0.f; }
}

__global__ __launch_bounds__(256) void bn_stats_kernel(const float* __restrict__ x0,
                                                       const float* __restrict__ x1) {
    int row  = blockIdx.x;
    int sidx = blockIdx.y;
    int tid  = threadIdx.x;
    const float* x = sidx ? x1 : x0;
    float4 v = ((const float4*)(x + (size_t)row * DD))[tid];
    float s = v.x + v.y + v.z + v.w;
    float q = v.x*v.x + v.y*v.y + v.z*v.z + v.w*v.w;
    #pragma unroll
    for (int o = 16; o > 0; o >>= 1) {
        s += __shfl_xor_sync(~0u, s, o);
        q += __shfl_xor_sync(~0u, q, o);
    }
    __shared__ float ss[8], qq[8];
    if ((tid & 31) == 0) { ss[tid >> 5] = s; qq[tid >> 5] = q; }
    __syncthreads();
    if (tid == 0) {
        float S = 0.f, Q = 0.f;
        #pragma unroll
        for (int w = 0; w < 8; w++) { S += ss[w]; Q += qq[w]; }
        atomicAdd(&g_bn_sum[sidx][row % 12], S);
        atomicAdd(&g_bn_sq [sidx][row % 12], Q);
    }
}

__global__ void bn_finalize_kernel(const float* __restrict__ bn_w, const float* __restrict__ bn_b) {
    int t = threadIdx.x;
    if (t < 24) {
        int s = t / 12, c = t % 12;
        const float CNT = 3072.0f * 1024.0f;
        float mean = g_bn_sum[s][c] / CNT;
        float var  = g_bn_sq [s][c] / CNT - mean * mean;
        float rstd = rsqrtf(var + 1e-5f);
        float sc   = rstd * bn_w[c];
        g_bn_scale[s][c] = sc;
        g_bn_shift[s][c] = bn_b[c] - mean * sc;
    }
}

__global__ __launch_bounds__(256) void bn_apply_cvt_kernel(const float* __restrict__ x0,
                                                           const float* __restrict__ x1,
                                                           const float* __restrict__ pos,
                                                           __nv_bfloat16* __restrict__ h0,
                                                           __nv_bfloat16* __restrict__ h1) {
    int row  = blockIdx.x;
    int sidx = blockIdx.y;
    int tid  = threadIdx.x;
    const float* x = sidx ? x1 : x0;
    __nv_bfloat16* hp = sidx ? h1 : h0;
    int c = row % 12;
    int b = row / 144;
    float sc = g_bn_scale[sidx][c], sh = g_bn_shift[sidx][c];
    float4 p = ((const float4*)(pos + ((size_t)(b * 12 + c)) * DD))[tid];
    float4 v = ((const float4*)(x + (size_t)row * DD))[tid];
    float y0 = v.x * sc + sh + p.x;
    float y1 = v.y * sc + sh + p.y;
    float y2 = v.z * sc + sh + p.z;
    float y3 = v.w * sc + sh + p.w;
    __nv_bfloat16 a0,a1,a2,a3,l0,l1,l2,l3;
    split_bf16(y0,a0,l0); split_bf16(y1,a1,l1); split_bf16(y2,a2,l2); split_bf16(y3,a3,l3);
    size_t base = (size_t)row * DD + tid * 4;
    __nv_bfloat162* hh = (__nv_bfloat162*)(hp + base);
    __nv_bfloat162* ll = (__nv_bfloat162*)(hp + UU + base);
    hh[0] = {a0,a1}; hh[1] = {a2,a3};
    ll[0] = {l0,l1}; ll[1] = {l2,l3};
}

// ---------------------------------------------------------------------------
// LayerNorm of concat(ar, at) -> bf16 hi/lo (lo at hi + 2U)
// ---------------------------------------------------------------------------
__global__ __launch_bounds__(256) void ln_cvt_kernel(const float* __restrict__ ar,
                                                     const float* __restrict__ at,
                                                     const float* __restrict__ lnw,
                                                     const float* __restrict__ lnb,
                                                     __nv_bfloat16* __restrict__ hi) {
    int row = blockIdx.x;
    int tid = threadIdx.x;
    int bh = row / 24, j = row % 24;
    const float* src = (j < 12) ? ar + ((size_t)bh * 12 + j) * DD
                                : at + ((size_t)bh * 12 + (j - 12)) * DD;
    float4 v = ((const float4*)src)[tid];
    float s = v.x + v.y + v.z + v.w;
    float q = v.x*v.x + v.y*v.y + v.z*v.z + v.w*v.w;
    #pragma unroll
    for (int o = 16; o > 0; o >>= 1) {
        s += __shfl_xor_sync(~0u, s, o);
        q += __shfl_xor_sync(~0u, q, o);
    }
    __shared__ float ss[8], qq[8], mom[2];
    if ((tid & 31) == 0) { ss[tid >> 5] = s; qq[tid >> 5] = q; }
    __syncthreads();
    if (tid == 0) {
        float S = 0.f, Q = 0.f;
        #pragma unroll
        for (int w = 0; w < 8; w++) { S += ss[w]; Q += qq[w]; }
        float mean = S / 1024.0f;
        float var  = Q / 1024.0f - mean * mean;
        mom[0] = mean;
        mom[1] = rsqrtf(var + 1e-5f);
    }
    __syncthreads();
    float mean = mom[0], rstd = mom[1];
    float4 w = ((const float4*)lnw)[tid];
    float4 bb = ((const float4*)lnb)[tid];
    float y0 = (v.x - mean) * rstd * w.x + bb.x;
    float y1 = (v.y - mean) * rstd * w.y + bb.y;
    float y2 = (v.z - mean) * rstd * w.z + bb.z;
    float y3 = (v.w - mean) * rstd * w.w + bb.w;
    __nv_bfloat16 a0,a1,a2,a3,l0,l1,l2,l3;
    split_bf16(y0,a0,l0); split_bf16(y1,a1,l1); split_bf16(y2,a2,l2); split_bf16(y3,a3,l3);
    size_t base = (size_t)row * DD + tid * 4;
    __nv_bfloat162* hh = (__nv_bfloat162*)(hi + base);
    __nv_bfloat162* ll = (__nv_bfloat162*)(hi + 2*UU + base);
    hh[0] = {a0,a1}; hh[1] = {a2,a3};
    ll[0] = {l0,l1}; ll[1] = {l2,l3};
}

// ---------------------------------------------------------------------------
// Fused attention + output: logits = (qg.x + dq + dk + c0)/32, softmax,
// out = attn @ value' + ob  written directly to d_out.
// ---------------------------------------------------------------------------
#define ATTN_SMEM ((24*1024 + 24*24 + 32) * sizeof(float))

__global__ __launch_bounds__(256) void attn_out_kernel(
    const float* __restrict__ qg_r, const float* __restrict__ qg_t,
    const __nv_bfloat16* __restrict__ xh_r, const __nv_bfloat16* __restrict__ xh_t,
    const float* __restrict__ valp,
    const float* __restrict__ ob,
    float* __restrict__ out) {
    extern __shared__ float sm[];
    float* xs  = sm;               // 24*1024 (x, then value')
    float* at  = sm + 24 * 1024;   // 24*24
    float* dks = at + 24 * 24;     // 24

    int bh  = blockIdx.x;
    int tid = threadIdx.x;
    int warp = tid >> 5, lane = tid & 31;

    // stage x = emb_norm concat (hi+lo reconstruction)
    for (int idx = tid; idx < 24 * 256; idx += 256) {
        int j = idx >> 8, p = idx & 255;
        const __nv_bfloat16* h = (j < 12) ? xh_r : xh_t;
        size_t base = ((size_t)bh * 12 + (j % 12)) * DD + p * 4;
        const __nv_bfloat162* hh = (const __nv_bfloat162*)(h + base);
        const __nv_bfloat162* ll = (const __nv_bfloat162*)(h + UU + base);
        __nv_bfloat162 a0 = hh[0], a1 = hh[1], b0 = ll[0], b1 = ll[1];
        float* xp = xs + j * 1024 + p * 4;
        xp[0] = __bfloat162float(a0.x) + __bfloat162float(b0.x);
        xp[1] = __bfloat162float(a0.y) + __bfloat162float(b0.y);
        xp[2] = __bfloat162float(a1.x) + __bfloat162float(b1.x);
        xp[3] = __bfloat162float(a1.y) + __bfloat162float(b1.y);
    }
    if (tid < 24) {
        int s = tid < 12 ? 0 : 1;
        dks[tid] = g_dk[s * M1 + bh * 12 + (tid % 12)];
    }
    __syncthreads();

    float c0v = g_misc[0];

    // logits: warp w handles q rows [3w, 3w+3)
    for (int qi = warp * 3; qi < warp * 3 + 3; qi++) {
        int s = (qi < 12) ? 0 : 1;
        const float* qrow = (s ? qg_t : qg_r) + ((size_t)bh * 12 + (qi % 12)) * DD;
        float dqv = g_dq[s * M1 + bh * 12 + (qi % 12)];
        float qv[32];
        #pragma unroll
        for (int t = 0; t < 32; t++) qv[t] = qrow[t * 32 + lane];
        for (int j = 0; j < 24; j++) {
            float sum = 0.f;
            #pragma unroll
            for (int t = 0; t < 32; t++) sum += qv[t] * xs[j * 1024 + t * 32 + lane];
            #pragma unroll
            for (int o = 16; o > 0; o >>= 1) sum += __shfl_xor_sync(~0u, sum, o);
            if (lane == 0) at[qi * 24 + j] = (sum + dqv + dks[j] + c0v) * 0.03125f;
        }
    }
    __syncthreads();

    // softmax per q-row
    for (int qi = warp * 3; qi < warp * 3 + 3; qi++) {
        float v = (lane < 24) ? at[qi * 24 + lane] : -3.0e38f;
        float m = v;
        #pragma unroll
        for (int o = 16; o > 0; o >>= 1) m = fmaxf(m, __shfl_xor_sync(~0u, m, o));
        float e = (lane < 24) ? expf(v - m) : 0.f;
        float s = e;
        #pragma unroll
        for (int o = 16; o > 0; o >>= 1) s += __shfl_xor_sync(~0u, s, o);
        if (lane < 24) at[qi * 24 + lane] = e / s;
    }
    __syncthreads();

    // stage value'
    const float* vbase = valp + (size_t)bh * 24 * DD;
    for (int i = tid; i < 24 * 256; i += 256)
        ((float4*)xs)[i] = ((const float4*)vbase)[i];
    __syncthreads();

    // out = attn @ value' + ob   (direct final output)
    int c0l = tid * 4;
    float4 obv = *(const float4*)(ob + c0l);
    for (int i = 0; i < 24; i++) {
        float4 acc = obv;
        #pragma unroll
        for (int j = 0; j < 24; j++) {
            float a = at[i * 24 + j];
            float4 v4 = *(const float4*)&xs[j * 1024 + c0l];
            acc.x += a * v4.x; acc.y += a * v4.y; acc.z += a * v4.z; acc.w += a * v4.w;
        }
        float* dst = out + ((i < 12) ? 0 : (size_t)M1 * DD)
                   + ((size_t)bh * 12 + (i % 12)) * DD + c0l;
        *(float4*)dst = acc;
    }
}

// ---------------------------------------------------------------------------
// Launch
// ---------------------------------------------------------------------------
extern "C" void kernel_launch(void* const* d_in, const int* in_sizes, int n_in,
                              void* d_out, int out_size) {
    const float* attn_rgb = (const float*)d_in[0];
    const float* attn_tir = (const float*)d_in[1];
    const float* pos_emb  = (const float*)d_in[2];
    const float* embed_w  = (const float*)d_in[3];
    const float* embed_b  = (const float*)d_in[4];
    const float* bn_w     = (const float*)d_in[5];
    const float* bn_b     = (const float*)d_in[6];
    const float* ln_w     = (const float*)d_in[7];
    const float* ln_b     = (const float*)d_in[8];
    const float* v_w      = (const float*)d_in[9];
    const float* v_b      = (const float*)d_in[10];
    const float* q_w      = (const float*)d_in[11];
    const float* q_b      = (const float*)d_in[12];
    const float* k_w      = (const float*)d_in[13];
    const float* k_b      = (const float*)d_in[14];
    const float* out_w    = (const float*)d_in[15];
    const float* out_b    = (const float*)d_in[16];
    float* out = (float*)d_out;

    __nv_bfloat16 *bf, *wbf;
    float *f32, *wf32, *zeros;
    cudaGetSymbolAddress((void**)&bf,    g_bf);
    cudaGetSymbolAddress((void**)&wbf,   g_wbf);
    cudaGetSymbolAddress((void**)&f32,   g_f32);
    cudaGetSymbolAddress((void**)&wf32,  g_wf32);
    cudaGetSymbolAddress((void**)&zeros, g_zeros);
    float *b2p;
    cudaGetSymbolAddress((void**)&b2p, g_b2);

    // bf16 weight arena slots
    __nv_bfloat16* ew  = wbf + 0*WU;    // hi; lo at +WU
    __nv_bfloat16* qwT = wbf + 2*WU;
    __nv_bfloat16* kwT = wbf + 4*WU;
    __nv_bfloat16* vwT = wbf + 6*WU;
    __nv_bfloat16* oww = wbf + 8*WU;
    __nv_bfloat16* GT  = wbf + 10*WU;
    __nv_bfloat16* W2  = wbf + 12*WU;
    // fp32 weight temps
    float* t_qwT = wf32 + 0*WU;
    float* t_kwT = wf32 + 1*WU;
    float* t_vwT = wf32 + 2*WU;
    float* t_GT  = wf32 + 3*WU;
    float* t_W2  = wf32 + 4*WU;
    // bf16 activation arena
    __nv_bfloat16* arh    = bf + 0*UU;   // -> ln later
    __nv_bfloat16* ath    = bf + 2*UU;
    __nv_bfloat16* embh_r = bf + 4*UU;
    __nv_bfloat16* embh_t = bf + 6*UU;
    __nv_bfloat16* lnh    = bf + 0*UU;   // 2U, lo at +2U
    // fp32 activation arena
    float* emb_r = f32 + 0*UU;   // -> qg_r
    float* emb_t = f32 + 1*UU;   // -> qg_t
    float* valp  = f32 + 2*UU;   // 2U
    float* qg_r  = f32 + 0*UU;
    float* qg_t  = f32 + 1*UU;

    cudaFuncSetAttribute(tc_gemm, cudaFuncAttributeMaxDynamicSharedMemorySize, GEMM_SMEM);
    cudaFuncSetAttribute(attn_out_kernel, cudaFuncAttributeMaxDynamicSharedMemorySize, (int)ATTN_SMEM);

    dim3 g1(4, M1 / 128);     // (4, 288)
    dim3 g2(4, M2 / 128);     // (4, 576)
    dim3 gw(4, 8);            // 1024-row GEMMs
    dim3 gbn(M1, 2);
    dim3 gt(32, 32), bt(32, 8);

    // ---- weight preprocessing ----
    transpose_kernel<<<gt, bt>>>(q_w, t_qwT);
    transpose_kernel<<<gt, bt>>>(k_w, t_kwT);
    transpose_kernel<<<gt, bt>>>(v_w, t_vwT);
    cvt_kernel<<<(int)(WU/1024), 256>>>(embed_w, ew,  ew  + WU);
    cvt_kernel<<<(int)(WU/1024), 256>>>(t_qwT,   qwT, qwT + WU);
    cvt_kernel<<<(int)(WU/1024), 256>>>(t_kwT,   kwT, kwT + WU);
    cvt_kernel<<<(int)(WU/1024), 256>>>(t_vwT,   vwT, vwT + WU);
    cvt_kernel<<<(int)(WU/1024), 256>>>(out_w,   oww, oww + WU);
    // GT = kw^T @ qw   (A=kwT, W=qwT)
    tc_gemm<<<gw, 256, GEMM_SMEM>>>(kwT, WU, qwT, zeros, t_GT);
    // W2 = ow @ vw     (A=ow, W=vwT)
    tc_gemm<<<gw, 256, GEMM_SMEM>>>(oww, WU, vwT, zeros, t_W2);
    cvt_kernel<<<(int)(WU/1024), 256>>>(t_GT, GT, GT + WU);
    cvt_kernel<<<(int)(WU/1024), 256>>>(t_W2, W2, W2 + WU);
    uv_kernel<<<5, 256>>>(q_w, k_w, q_b, k_b);
    bias2_kernel<<<128, 256>>>(out_w, v_b);

    // ---- input splits ----
    cvt_kernel<<<(int)(UU/1024), 256>>>(attn_rgb, arh, arh + UU);
    cvt_kernel<<<(int)(UU/1024), 256>>>(attn_tir, ath, ath + UU);

    // ---- embedding GEMMs -> fp32 ----
    tc_gemm<<<g1, 256, GEMM_SMEM>>>(arh, UU, ew, embed_b, emb_r);
    tc_gemm<<<g1, 256, GEMM_SMEM>>>(ath, UU, ew, embed_b, emb_t);

    // ---- BatchNorm + pos -> emb bf16 hi/lo ----
    bn_zero_kernel<<<1, 32>>>();
    bn_stats_kernel<<<gbn, 256>>>(emb_r, emb_t);
    bn_finalize_kernel<<<1, 32>>>(bn_w, bn_b);
    bn_apply_cvt_kernel<<<gbn, 256>>>(emb_r, emb_t, pos_emb, embh_r, embh_t);

    // ---- LayerNorm + fused value-out GEMM (W2) ----
    ln_cvt_kernel<<<M2, 256>>>(attn_rgb, attn_tir, ln_w, ln_b, lnh);
    tc_gemm<<<g2, 256, GEMM_SMEM>>>(lnh, 2*UU, W2, b2p, valp);

    // ---- bias-term GEMVs + qg projections (replaces q and k GEMMs) ----
    dqdk_kernel<<<gbn, 256>>>(embh_r, embh_t);
    tc_gemm<<<g1, 256, GEMM_SMEM>>>(embh_r, UU, GT, zeros, qg_r);
    tc_gemm<<<g1, 256, GEMM_SMEM>>>(embh_t, UU, GT, zeros, qg_t);

    // ---- attention + direct output ----
    attn_out_kernel<<<BH, 256, ATTN_SMEM>>>(qg_r, qg_t, embh_r, embh_t, valp, out_b, out);
}

// round 10
// speedup vs baseline: 3.3413x; 1.0947x over previous
#include <cuda_runtime.h>
#include <cuda_bf16.h>
#include <cstdint>
#include <cstddef>

#define BB   256
#define HN   12
#define N1   12
#define DD   1024
#define BH   (BB*HN)
#define M1   (BH*N1)         // 36864
#define M2   (BH*2*N1)       // 73728

#define UU   ((size_t)M1 * DD)
#define WU   ((size_t)DD * DD)

// ---------------------------------------------------------------------------
// Static scratch
// fp32 arena (6 U): 0:emb_r->qg_r 1:emb_t->qg_t 2..3:lnf 4..5:value'
// bf16 arena (4 U): embh_r hi/lo, embh_t hi/lo
// ---------------------------------------------------------------------------
__device__ float g_f32[6 * UU];
__device__ __nv_bfloat16 g_bf[4 * UU];
__device__ __nv_bfloat16 g_wbf[10 * WU];   // qwT h/l kwT h/l vwT h/l ow h/l GT h/l
__device__ float g_wf32[5 * WU];           // t_qwT t_kwT t_vwT t_GT t_W2

__device__ float g_bn_sum[2][12];
__device__ float g_bn_sq [2][12];
__device__ float g_bn_scale[2][12];
__device__ float g_bn_shift[2][12];

__device__ float g_u[DD];
__device__ float g_v[DD];
__device__ float g_b2[DD];
__device__ float g_misc[4];
__device__ float g_zeros[DD];
__device__ float g_dq[2 * M1];
__device__ float g_dk[2 * M1];

// ---------------------------------------------------------------------------
// Helpers
// ---------------------------------------------------------------------------
__device__ __forceinline__ uint32_t smem_to_u32(const void* p) {
    uint32_t a;
    asm("{ .reg .u64 t; cvta.to.shared.u64 t, %1; cvt.u32.u64 %0, t; }" : "=r"(a) : "l"(p));
    return a;
}
__device__ __forceinline__ void cp16(uint32_t dst, const void* src) {
    asm volatile("cp.async.cg.shared.global [%0], [%1], 16;\n" :: "r"(dst), "l"(src));
}
__device__ __forceinline__ void cp_commit() {
    asm volatile("cp.async.commit_group;\n" ::: "memory");
}
__device__ __forceinline__ void ldsm4(uint32_t addr, uint32_t& r0, uint32_t& r1,
                                      uint32_t& r2, uint32_t& r3) {
    asm volatile("ldmatrix.sync.aligned.m8n8.x4.shared.b16 {%0,%1,%2,%3}, [%4];"
        : "=r"(r0), "=r"(r1), "=r"(r2), "=r"(r3) : "r"(addr));
}
__device__ __forceinline__ uint32_t lds_tf32(uint32_t addr) {
    float v;
    asm volatile("ld.shared.b32 %0, [%1];" : "=f"(v) : "r"(addr));
    uint32_t o;
    asm("cvt.rna.tf32.f32 %0, %1;" : "=r"(o) : "f"(v));
    return o;
}
__device__ __forceinline__ void mma16816(float* c, const uint32_t* a, uint32_t b0, uint32_t b1) {
    asm volatile("mma.sync.aligned.m16n8k16.row.col.f32.bf16.bf16.f32 "
        "{%0,%1,%2,%3}, {%4,%5,%6,%7}, {%8,%9}, {%0,%1,%2,%3};"
        : "+f"(c[0]), "+f"(c[1]), "+f"(c[2]), "+f"(c[3])
        : "r"(a[0]), "r"(a[1]), "r"(a[2]), "r"(a[3]), "r"(b0), "r"(b1));
}
__device__ __forceinline__ void mma1688t(float* c, const uint32_t* a, uint32_t b0, uint32_t b1) {
    asm volatile("mma.sync.aligned.m16n8k8.row.col.f32.tf32.tf32.f32 "
        "{%0,%1,%2,%3}, {%4,%5,%6,%7}, {%8,%9}, {%0,%1,%2,%3};"
        : "+f"(c[0]), "+f"(c[1]), "+f"(c[2]), "+f"(c[3])
        : "r"(a[0]), "r"(a[1]), "r"(a[2]), "r"(a[3]), "r"(b0), "r"(b1));
}

// bf16 tile: rows x 64B; seg(16B) ^= (row>>1)&3
__device__ __forceinline__ uint32_t swz(int r, int s) {
    return (uint32_t)(r * 64 + ((s ^ ((r >> 1) & 3)) << 4));
}
// tf32 tile: rows x 128B; seg(16B, 0..7) ^= row&7
__device__ __forceinline__ uint32_t swzt(int r, int s) {
    return (uint32_t)(r * 128 + ((s ^ (r & 7)) << 4));
}

__device__ __forceinline__ void split_bf16(float x, __nv_bfloat16& h, __nv_bfloat16& l) {
    h = __float2bfloat16(x);
    l = __float2bfloat16(x - __bfloat162float(h));
}

__global__ __launch_bounds__(256) void cvt_kernel(const float* __restrict__ x,
                                                  __nv_bfloat16* __restrict__ hi,
                                                  __nv_bfloat16* __restrict__ lo) {
    size_t idx = (size_t)blockIdx.x * 256 + threadIdx.x;
    float4 v = ((const float4*)x)[idx];
    __nv_bfloat16 h0,h1,h2,h3,l0,l1,l2,l3;
    split_bf16(v.x,h0,l0); split_bf16(v.y,h1,l1); split_bf16(v.z,h2,l2); split_bf16(v.w,h3,l3);
    __nv_bfloat162* hp = (__nv_bfloat162*)hi;
    __nv_bfloat162* lp = (__nv_bfloat162*)lo;
    hp[idx*2]   = {h0,h1}; hp[idx*2+1] = {h2,h3};
    lp[idx*2]   = {l0,l1}; lp[idx*2+1] = {l2,l3};
}

__global__ void transpose_kernel(const float* __restrict__ src, float* __restrict__ dst) {
    __shared__ float t[32][33];
    int x = blockIdx.x * 32 + threadIdx.x;
    int y = blockIdx.y * 32 + threadIdx.y;
    #pragma unroll
    for (int r = 0; r < 4; r++)
        t[threadIdx.y + r * 8][threadIdx.x] = src[(size_t)(y + r * 8) * DD + x];
    __syncthreads();
    int x2 = blockIdx.y * 32 + threadIdx.x;
    int y2 = blockIdx.x * 32 + threadIdx.y;
    #pragma unroll
    for (int r = 0; r < 4; r++)
        dst[(size_t)(y2 + r * 8) * DD + x2] = t[threadIdx.x][threadIdx.y + r * 8];
}

// ---------------------------------------------------------------------------
// bf16x3 GEMM (proven): C = A@W^T + bias. A hi/lo (lo at +loD), W hi/lo (+WU)
// BM=128 BN=256 BK=32, 256 thr, 8 warps 2x4, warp tile 64x64.
// ---------------------------------------------------------------------------
#define STAGE_BYTES 49152
#define GEMM_SMEM   (2 * STAGE_BYTES)

__global__ __launch_bounds__(256, 1) void tc_gemm(
    const __nv_bfloat16* __restrict__ A0h, size_t loD,
    const __nv_bfloat16* __restrict__ Wh,
    const float* __restrict__ bias, float* __restrict__ C)
{
    extern __shared__ char smem[];
    const uint32_t sb = smem_to_u32(smem);
    const int tid = threadIdx.x;
    const int bm = blockIdx.y * 128;
    const int bn = blockIdx.x * 256;

    const int lr = tid >> 1;
    const int s0 = (tid & 1) * 2;
    const char* aP = (const char*)(A0h + (size_t)(bm + lr) * DD);
    const char* wP = (const char*)(Wh + (size_t)(bn + tid) * DD);
    const size_t loB  = loD * 2;
    const size_t wLoB = WU * 2;

    const uint32_t aD0 = swz(lr, s0);
    const uint32_t aD1 = swz(lr, s0 + 1);
    uint32_t wD[4];
    #pragma unroll
    for (int j = 0; j < 4; j++) wD[j] = swz(tid, j);

    const int wid = tid >> 5, lane = tid & 31;
    const int wm = wid & 1, wn = wid >> 1;
    const int rowA = wm * 64 + (lane & 15);
    const int segA = lane >> 4;
    const int xA = (rowA >> 1) & 3;
    const uint32_t aRowOff = rowA * 64;
    uint32_t aCol[2];
    aCol[0] = (uint32_t)(((segA + 0) ^ xA) << 4);
    aCol[1] = (uint32_t)(((segA + 2) ^ xA) << 4);
    const int rowB = wn * 64 + (lane & 7) + ((lane >> 4) << 3);
    const int segB = (lane >> 3) & 1;
    const int xB = (rowB >> 1) & 3;
    const uint32_t bRowOff = rowB * 64;
    uint32_t bCol[2];
    bCol[0] = (uint32_t)(((segB + 0) ^ xB) << 4);
    bCol[1] = (uint32_t)(((segB + 2) ^ xB) << 4);

    float acc[4][8][4];
    #pragma unroll
    for (int i = 0; i < 4; i++)
        #pragma unroll
        for (int j = 0; j < 8; j++)
            #pragma unroll
            for (int t = 0; t < 4; t++) acc[i][j][t] = 0.f;

    auto load_stage = [&](int c, int st) {
        uint32_t B = sb + st * STAGE_BYTES;
        size_t off = (size_t)c * 64;
        cp16(B + aD0,        aP + off + s0 * 16);
        cp16(B + aD1,        aP + off + s0 * 16 + 16);
        cp16(B + 8192 + aD0, aP + loB + off + s0 * 16);
        cp16(B + 8192 + aD1, aP + loB + off + s0 * 16 + 16);
        #pragma unroll
        for (int j = 0; j < 4; j++) {
            cp16(B + 16384 + wD[j], wP + off + j * 16);
            cp16(B + 32768 + wD[j], wP + wLoB + off + j * 16);
        }
        cp_commit();
    };

    auto do_mmas = [&](uint32_t a[4][4], uint32_t b[4][4]) {
        #pragma unroll
        for (int mi = 0; mi < 4; mi++)
            #pragma unroll
            for (int p = 0; p < 4; p++) {
                mma16816(acc[mi][2*p],   a[mi], b[p][0], b[p][1]);
                mma16816(acc[mi][2*p+1], a[mi], b[p][2], b[p][3]);
            }
    };

    auto compute_stage = [&](int st) {
        uint32_t base = sb + st * STAGE_BYTES;
        uint32_t aH = base + aRowOff;
        uint32_t aL = aH + 8192;
        uint32_t bH = base + 16384 + bRowOff;
        uint32_t bL = bH + 16384;
        #pragma unroll
        for (int k = 0; k < 2; k++) {
            uint32_t a[4][4], b[4][4];
            #pragma unroll
            for (int p = 0; p < 4; p++)
                ldsm4(bH + p * 1024 + bCol[k], b[p][0], b[p][1], b[p][2], b[p][3]);
            #pragma unroll
            for (int mi = 0; mi < 4; mi++)
                ldsm4(aH + mi * 1024 + aCol[k], a[mi][0], a[mi][1], a[mi][2], a[mi][3]);
            do_mmas(a, b);
            #pragma unroll
            for (int mi = 0; mi < 4; mi++)
                ldsm4(aL + mi * 1024 + aCol[k], a[mi][0], a[mi][1], a[mi][2], a[mi][3]);
            do_mmas(a, b);
            #pragma unroll
            for (int p = 0; p < 4; p++)
                ldsm4(bL + p * 1024 + bCol[k], b[p][0], b[p][1], b[p][2], b[p][3]);
            #pragma unroll
            for (int mi = 0; mi < 4; mi++)
                ldsm4(aH + mi * 1024 + aCol[k], a[mi][0], a[mi][1], a[mi][2], a[mi][3]);
            do_mmas(a, b);
        }
    };

    load_stage(0, 0);
    #pragma unroll 1
    for (int c = 0; c < 32; c++) {
        int st = c & 1;
        if (c + 1 < 32) {
            load_stage(c + 1, st ^ 1);
            asm volatile("cp.async.wait_group 1;" ::: "memory");
        } else {
            asm volatile("cp.async.wait_group 0;" ::: "memory");
        }
        __syncthreads();
        compute_stage(st);
        __syncthreads();
    }

    const int r0   = bm + wm * 64 + (lane >> 2);
    const int col0 = bn + wn * 64 + (lane & 3) * 2;
    #pragma unroll
    for (int nf = 0; nf < 8; nf++) {
        int col = col0 + nf * 8;
        float bx = bias[col], by = bias[col + 1];
        #pragma unroll
        for (int mi = 0; mi < 4; mi++) {
            float* p0 = C + (size_t)(r0 + mi * 16) * DD + col;
            float2 v0 = { acc[mi][nf][0] + bx, acc[mi][nf][1] + by };
            float2 v1 = { acc[mi][nf][2] + bx, acc[mi][nf][3] + by };
            *(float2*)p0 = v0;
            *(float2*)(p0 + 8 * DD) = v1;
        }
    }
}

// ---------------------------------------------------------------------------
// tf32 single-term GEMM: C = A@W^T + bias. A,W plain fp32 (rna-rounded in reg).
// Same tiling. Stage: A 16KB + W 32KB = 48KB.
// ---------------------------------------------------------------------------
__global__ __launch_bounds__(256, 1) void tc_gemm_tf32(
    const float* __restrict__ A, const float* __restrict__ W,
    const float* __restrict__ bias, float* __restrict__ C)
{
    extern __shared__ char smem[];
    const uint32_t sb = smem_to_u32(smem);
    const int tid = threadIdx.x;
    const int bm = blockIdx.y * 128;
    const int bn = blockIdx.x * 256;

    const int lr = tid >> 1;
    const int s0 = (tid & 1) * 4;
    const char* aP = (const char*)(A + (size_t)(bm + lr) * DD);
    const char* wP = (const char*)(W + (size_t)(bn + tid) * DD);
    uint32_t aD[4], wD[8];
    #pragma unroll
    for (int j = 0; j < 4; j++) aD[j] = swzt(lr, s0 + j);
    #pragma unroll
    for (int j = 0; j < 8; j++) wD[j] = swzt(tid, j);

    const int wid = tid >> 5, lane = tid & 31;
    const int wm = wid & 1, wn = wid >> 1;
    const int tR = lane >> 2;
    const uint32_t tC4 = (uint32_t)((lane & 3) * 4);

    float acc[4][8][4];
    #pragma unroll
    for (int i = 0; i < 4; i++)
        #pragma unroll
        for (int j = 0; j < 8; j++)
            #pragma unroll
            for (int t = 0; t < 4; t++) acc[i][j][t] = 0.f;

    auto load_stage = [&](int c, int st) {
        uint32_t B = sb + st * STAGE_BYTES;
        size_t off = (size_t)c * 128;
        #pragma unroll
        for (int j = 0; j < 4; j++)
            cp16(B + aD[j], aP + off + (s0 + j) * 16);
        #pragma unroll
        for (int j = 0; j < 8; j++)
            cp16(B + 16384 + wD[j], wP + off + j * 16);
        cp_commit();
    };

    auto compute_stage = [&](int st) {
        uint32_t base = sb + st * STAGE_BYTES;
        #pragma unroll
        for (int k8 = 0; k8 < 4; k8++) {
            uint32_t bF[8][2], aF[4][4];
            #pragma unroll
            for (int nf = 0; nf < 8; nf++) {
                int n = wn * 64 + nf * 8 + tR;
                uint32_t nb = base + 16384 + n * 128 + tC4;
                bF[nf][0] = lds_tf32(nb + (((k8*2)     ^ (n & 7)) << 4));
                bF[nf][1] = lds_tf32(nb + (((k8*2 + 1) ^ (n & 7)) << 4));
            }
            #pragma unroll
            for (int mi = 0; mi < 4; mi++) {
                #pragma unroll
                for (int h = 0; h < 2; h++) {
                    int r = wm * 64 + mi * 16 + h * 8 + tR;
                    uint32_t rb = base + r * 128 + tC4;
                    aF[mi][h]     = lds_tf32(rb + (((k8*2)     ^ (r & 7)) << 4));
                    aF[mi][h + 2] = lds_tf32(rb + (((k8*2 + 1) ^ (r & 7)) << 4));
                }
            }
            #pragma unroll
            for (int mi = 0; mi < 4; mi++)
                #pragma unroll
                for (int nf = 0; nf < 8; nf++)
                    mma1688t(acc[mi][nf], aF[mi], bF[nf][0], bF[nf][1]);
        }
    };

    load_stage(0, 0);
    #pragma unroll 1
    for (int c = 0; c < 32; c++) {
        int st = c & 1;
        if (c + 1 < 32) {
            load_stage(c + 1, st ^ 1);
            asm volatile("cp.async.wait_group 1;" ::: "memory");
        } else {
            asm volatile("cp.async.wait_group 0;" ::: "memory");
        }
        __syncthreads();
        compute_stage(st);
        __syncthreads();
    }

    const int r0   = bm + wm * 64 + (lane >> 2);
    const int col0 = bn + wn * 64 + (lane & 3) * 2;
    #pragma unroll
    for (int nf = 0; nf < 8; nf++) {
        int col = col0 + nf * 8;
        float bx = bias[col], by = bias[col + 1];
        #pragma unroll
        for (int mi = 0; mi < 4; mi++) {
            float* p0 = C + (size_t)(r0 + mi * 16) * DD + col;
            float2 v0 = { acc[mi][nf][0] + bx, acc[mi][nf][1] + by };
            float2 v1 = { acc[mi][nf][2] + bx, acc[mi][nf][3] + by };
            *(float2*)p0 = v0;
            *(float2*)(p0 + 8 * DD) = v1;
        }
    }
}

// ---------------------------------------------------------------------------
// Bias algebra
// ---------------------------------------------------------------------------
__global__ __launch_bounds__(256) void uv_kernel(const float* __restrict__ qw,
                                                 const float* __restrict__ kw,
                                                 const float* __restrict__ qb,
                                                 const float* __restrict__ kb) {
    if (blockIdx.x < 4) {
        int d = blockIdx.x * 256 + threadIdx.x;
        float su = 0.f, sv = 0.f;
        for (int c = 0; c < DD; c++) {
            su += qw[(size_t)c * DD + d] * kb[c];
            sv += kw[(size_t)c * DD + d] * qb[c];
        }
        g_u[d] = su;
        g_v[d] = sv;
    } else {
        int tid = threadIdx.x;
        float s = qb[tid]*kb[tid] + qb[tid+256]*kb[tid+256]
                + qb[tid+512]*kb[tid+512] + qb[tid+768]*kb[tid+768];
        #pragma unroll
        for (int o = 16; o > 0; o >>= 1) s += __shfl_xor_sync(~0u, s, o);
        __shared__ float ss[8];
        if ((tid & 31) == 0) ss[tid >> 5] = s;
        __syncthreads();
        if (tid == 0) {
            float S = 0.f;
            #pragma unroll
            for (int w = 0; w < 8; w++) S += ss[w];
            g_misc[0] = S;
        }
    }
}

__global__ __launch_bounds__(256) void bias2_kernel(const float* __restrict__ ow,
                                                    const float* __restrict__ vb) {
    int wid = threadIdx.x >> 5, lane = threadIdx.x & 31;
    int row = blockIdx.x * 8 + wid;
    const float* r = ow + (size_t)row * DD;
    float s = 0.f;
    for (int c = lane; c < DD; c += 32) s += r[c] * vb[c];
    #pragma unroll
    for (int o = 16; o > 0; o >>= 1) s += __shfl_xor_sync(~0u, s, o);
    if (lane == 0) g_b2[row] = s;
}

__global__ __launch_bounds__(256) void dqdk_kernel(const __nv_bfloat16* __restrict__ h0,
                                                   const __nv_bfloat16* __restrict__ h1) {
    int row = blockIdx.x, sidx = blockIdx.y, tid = threadIdx.x;
    const __nv_bfloat16* h = sidx ? h1 : h0;
    size_t base = (size_t)row * DD + tid * 4;
    const __nv_bfloat162* hh = (const __nv_bfloat162*)(h + base);
    const __nv_bfloat162* ll = (const __nv_bfloat162*)(h + UU + base);
    __nv_bfloat162 a0 = hh[0], a1 = hh[1], b0 = ll[0], b1 = ll[1];
    float x0 = __bfloat162float(a0.x) + __bfloat162float(b0.x);
    float x1 = __bfloat162float(a0.y) + __bfloat162float(b0.y);
    float x2 = __bfloat162float(a1.x) + __bfloat162float(b1.x);
    float x3 = __bfloat162float(a1.y) + __bfloat162float(b1.y);
    float4 u4 = ((const float4*)g_u)[tid];
    float4 v4 = ((const float4*)g_v)[tid];
    float su = x0*u4.x + x1*u4.y + x2*u4.z + x3*u4.w;
    float sv = x0*v4.x + x1*v4.y + x2*v4.z + x3*v4.w;
    #pragma unroll
    for (int o = 16; o > 0; o >>= 1) {
        su += __shfl_xor_sync(~0u, su, o);
        sv += __shfl_xor_sync(~0u, sv, o);
    }
    __shared__ float ssu[8], ssv[8];
    if ((tid & 31) == 0) { ssu[tid >> 5] = su; ssv[tid >> 5] = sv; }
    __syncthreads();
    if (tid == 0) {
        float SU = 0.f, SV = 0.f;
        #pragma unroll
        for (int w = 0; w < 8; w++) { SU += ssu[w]; SV += ssv[w]; }
        g_dq[sidx * M1 + row] = SU;
        g_dk[sidx * M1 + row] = SV;
    }
}

// ---------------------------------------------------------------------------
// BatchNorm
// ---------------------------------------------------------------------------
__global__ void bn_zero_kernel() {
    int t = threadIdx.x;
    if (t < 24) { ((float*)g_bn_sum)[t] = 0.f; ((float*)g_bn_sq)[t] = 0.f; }
}

__global__ __launch_bounds__(256) void bn_stats_kernel(const float* __restrict__ x0,
                                                       const float* __restrict__ x1) {
    int row  = blockIdx.x;
    int sidx = blockIdx.y;
    int tid  = threadIdx.x;
    const float* x = sidx ? x1 : x0;
    float4 v = ((const float4*)(x + (size_t)row * DD))[tid];
    float s = v.x + v.y + v.z + v.w;
    float q = v.x*v.x + v.y*v.y + v.z*v.z + v.w*v.w;
    #pragma unroll
    for (int o = 16; o > 0; o >>= 1) {
        s += __shfl_xor_sync(~0u, s, o);
        q += __shfl_xor_sync(~0u, q, o);
    }
    __shared__ float ss[8], qq[8];
    if ((tid & 31) == 0) { ss[tid >> 5] = s; qq[tid >> 5] = q; }
    __syncthreads();
    if (tid == 0) {
        float S = 0.f, Q = 0.f;
        #pragma unroll
        for (int w = 0; w < 8; w++) { S += ss[w]; Q += qq[w]; }
        atomicAdd(&g_bn_sum[sidx][row % 12], S);
        atomicAdd(&g_bn_sq [sidx][row % 12], Q);
    }
}

__global__ void bn_finalize_kernel(const float* __restrict__ bn_w, const float* __restrict__ bn_b) {
    int t = threadIdx.x;
    if (t < 24) {
        int s = t / 12, c = t % 12;
        const float CNT = 3072.0f * 1024.0f;
        float mean = g_bn_sum[s][c] / CNT;
        float var  = g_bn_sq [s][c] / CNT - mean * mean;
        float rstd = rsqrtf(var + 1e-5f);
        float sc   = rstd * bn_w[c];
        g_bn_scale[s][c] = sc;
        g_bn_shift[s][c] = bn_b[c] - mean * sc;
    }
}

__global__ __launch_bounds__(256) void bn_apply_cvt_kernel(const float* __restrict__ x0,
                                                           const float* __restrict__ x1,
                                                           const float* __restrict__ pos,
                                                           __nv_bfloat16* __restrict__ h0,
                                                           __nv_bfloat16* __restrict__ h1) {
    int row  = blockIdx.x;
    int sidx = blockIdx.y;
    int tid  = threadIdx.x;
    const float* x = sidx ? x1 : x0;
    __nv_bfloat16* hp = sidx ? h1 : h0;
    int c = row % 12;
    int b = row / 144;
    float sc = g_bn_scale[sidx][c], sh = g_bn_shift[sidx][c];
    float4 p = ((const float4*)(pos + ((size_t)(b * 12 + c)) * DD))[tid];
    float4 v = ((const float4*)(x + (size_t)row * DD))[tid];
    float y0 = v.x * sc + sh + p.x;
    float y1 = v.y * sc + sh + p.y;
    float y2 = v.z * sc + sh + p.z;
    float y3 = v.w * sc + sh + p.w;
    __nv_bfloat16 a0,a1,a2,a3,l0,l1,l2,l3;
    split_bf16(y0,a0,l0); split_bf16(y1,a1,l1); split_bf16(y2,a2,l2); split_bf16(y3,a3,l3);
    size_t base = (size_t)row * DD + tid * 4;
    __nv_bfloat162* hh = (__nv_bfloat162*)(hp + base);
    __nv_bfloat162* ll = (__nv_bfloat162*)(hp + UU + base);
    hh[0] = {a0,a1}; hh[1] = {a2,a3};
    ll[0] = {l0,l1}; ll[1] = {l2,l3};
}

// ---------------------------------------------------------------------------
// LayerNorm of concat(ar, at) -> fp32 (tf32 GEMM consumes it)
// ---------------------------------------------------------------------------
__global__ __launch_bounds__(256) void ln_kernel(const float* __restrict__ ar,
                                                 const float* __restrict__ at,
                                                 const float* __restrict__ lnw,
                                                 const float* __restrict__ lnb,
                                                 float* __restrict__ out) {
    int row = blockIdx.x;
    int tid = threadIdx.x;
    int bh = row / 24, j = row % 24;
    const float* src = (j < 12) ? ar + ((size_t)bh * 12 + j) * DD
                                : at + ((size_t)bh * 12 + (j - 12)) * DD;
    float4 v = ((const float4*)src)[tid];
    float s = v.x + v.y + v.z + v.w;
    float q = v.x*v.x + v.y*v.y + v.z*v.z + v.w*v.w;
    #pragma unroll
    for (int o = 16; o > 0; o >>= 1) {
        s += __shfl_xor_sync(~0u, s, o);
        q += __shfl_xor_sync(~0u, q, o);
    }
    __shared__ float ss[8], qq[8], mom[2];
    if ((tid & 31) == 0) { ss[tid >> 5] = s; qq[tid >> 5] = q; }
    __syncthreads();
    if (tid == 0) {
        float S = 0.f, Q = 0.f;
        #pragma unroll
        for (int w = 0; w < 8; w++) { S += ss[w]; Q += qq[w]; }
        float mean = S / 1024.0f;
        float var  = Q / 1024.0f - mean * mean;
        mom[0] = mean;
        mom[1] = rsqrtf(var + 1e-5f);
    }
    __syncthreads();
    float mean = mom[0], rstd = mom[1];
    float4 w = ((const float4*)lnw)[tid];
    float4 bb = ((const float4*)lnb)[tid];
    float4 o4;
    o4.x = (v.x - mean) * rstd * w.x + bb.x;
    o4.y = (v.y - mean) * rstd * w.y + bb.y;
    o4.z = (v.z - mean) * rstd * w.z + bb.z;
    o4.w = (v.w - mean) * rstd * w.w + bb.w;
    ((float4*)(out + (size_t)row * DD))[tid] = o4;
}

// ---------------------------------------------------------------------------
// Fused attention + output
// ---------------------------------------------------------------------------
#define ATTN_SMEM ((24*1024 + 24*24 + 32) * sizeof(float))

__global__ __launch_bounds__(256) void attn_out_kernel(
    const float* __restrict__ qg_r, const float* __restrict__ qg_t,
    const __nv_bfloat16* __restrict__ xh_r, const __nv_bfloat16* __restrict__ xh_t,
    const float* __restrict__ valp,
    const float* __restrict__ ob,
    float* __restrict__ out) {
    extern __shared__ float sm[];
    float* xs  = sm;
    float* at  = sm + 24 * 1024;
    float* dks = at + 24 * 24;

    int bh  = blockIdx.x;
    int tid = threadIdx.x;
    int warp = tid >> 5, lane = tid & 31;

    for (int idx = tid; idx < 24 * 256; idx += 256) {
        int j = idx >> 8, p = idx & 255;
        const __nv_bfloat16* h = (j < 12) ? xh_r : xh_t;
        size_t base = ((size_t)bh * 12 + (j % 12)) * DD + p * 4;
        const __nv_bfloat162* hh = (const __nv_bfloat162*)(h + base);
        const __nv_bfloat162* ll = (const __nv_bfloat162*)(h + UU + base);
        __nv_bfloat162 a0 = hh[0], a1 = hh[1], b0 = ll[0], b1 = ll[1];
        float* xp = xs + j * 1024 + p * 4;
        xp[0] = __bfloat162float(a0.x) + __bfloat162float(b0.x);
        xp[1] = __bfloat162float(a0.y) + __bfloat162float(b0.y);
        xp[2] = __bfloat162float(a1.x) + __bfloat162float(b1.x);
        xp[3] = __bfloat162float(a1.y) + __bfloat162float(b1.y);
    }
    if (tid < 24) {
        int s = tid < 12 ? 0 : 1;
        dks[tid] = g_dk[s * M1 + bh * 12 + (tid % 12)];
    }
    __syncthreads();

    float c0v = g_misc[0];

    for (int qi = warp * 3; qi < warp * 3 + 3; qi++) {
        int s = (qi < 12) ? 0 : 1;
        const float* qrow = (s ? qg_t : qg_r) + ((size_t)bh * 12 + (qi % 12)) * DD;
        float dqv = g_dq[s * M1 + bh * 12 + (qi % 12)];
        float qv[32];
        #pragma unroll
        for (int t = 0; t < 32; t++) qv[t] = qrow[t * 32 + lane];
        for (int j = 0; j < 24; j++) {
            float sum = 0.f;
            #pragma unroll
            for (int t = 0; t < 32; t++) sum += qv[t] * xs[j * 1024 + t * 32 + lane];
            #pragma unroll
            for (int o = 16; o > 0; o >>= 1) sum += __shfl_xor_sync(~0u, sum, o);
            if (lane == 0) at[qi * 24 + j] = (sum + dqv + dks[j] + c0v) * 0.03125f;
        }
    }
    __syncthreads();

    for (int qi = warp * 3; qi < warp * 3 + 3; qi++) {
        float v = (lane < 24) ? at[qi * 24 + lane] : -3.0e38f;
        float m = v;
        #pragma unroll
        for (int o = 16; o > 0; o >>= 1) m = fmaxf(m, __shfl_xor_sync(~0u, m, o));
        float e = (lane < 24) ? expf(v - m) : 0.f;
        float s = e;
        #pragma unroll
        for (int o = 16; o > 0; o >>= 1) s += __shfl_xor_sync(~0u, s, o);
        if (lane < 24) at[qi * 24 + lane] = e / s;
    }
    __syncthreads();

    const float* vbase = valp + (size_t)bh * 24 * DD;
    for (int i = tid; i < 24 * 256; i += 256)
        ((float4*)xs)[i] = ((const float4*)vbase)[i];
    __syncthreads();

    int c0l = tid * 4;
    float4 obv = *(const float4*)(ob + c0l);
    for (int i = 0; i < 24; i++) {
        float4 acc = obv;
        #pragma unroll
        for (int j = 0; j < 24; j++) {
            float a = at[i * 24 + j];
            float4 v4 = *(const float4*)&xs[j * 1024 + c0l];
            acc.x += a * v4.x; acc.y += a * v4.y; acc.z += a * v4.z; acc.w += a * v4.w;
        }
        float* dst = out + ((i < 12) ? 0 : (size_t)M1 * DD)
                   + ((size_t)bh * 12 + (i % 12)) * DD + c0l;
        *(float4*)dst = acc;
    }
}

// ---------------------------------------------------------------------------
// Launch
// ---------------------------------------------------------------------------
extern "C" void kernel_launch(void* const* d_in, const int* in_sizes, int n_in,
                              void* d_out, int out_size) {
    const float* attn_rgb = (const float*)d_in[0];
    const float* attn_tir = (const float*)d_in[1];
    const float* pos_emb  = (const float*)d_in[2];
    const float* embed_w  = (const float*)d_in[3];
    const float* embed_b  = (const float*)d_in[4];
    const float* bn_w     = (const float*)d_in[5];
    const float* bn_b     = (const float*)d_in[6];
    const float* ln_w     = (const float*)d_in[7];
    const float* ln_b     = (const float*)d_in[8];
    const float* v_w      = (const float*)d_in[9];
    const float* v_b      = (const float*)d_in[10];
    const float* q_w      = (const float*)d_in[11];
    const float* q_b      = (const float*)d_in[12];
    const float* k_w      = (const float*)d_in[13];
    const float* k_b      = (const float*)d_in[14];
    const float* out_w    = (const float*)d_in[15];
    const float* out_b    = (const float*)d_in[16];
    float* out = (float*)d_out;

    __nv_bfloat16 *bf, *wbf;
    float *f32, *wf32, *zeros, *b2p;
    cudaGetSymbolAddress((void**)&bf,    g_bf);
    cudaGetSymbolAddress((void**)&wbf,   g_wbf);
    cudaGetSymbolAddress((void**)&f32,   g_f32);
    cudaGetSymbolAddress((void**)&wf32,  g_wf32);
    cudaGetSymbolAddress((void**)&zeros, g_zeros);
    cudaGetSymbolAddress((void**)&b2p,   g_b2);

    __nv_bfloat16* qwT = wbf + 0*WU;   // hi; lo at +WU
    __nv_bfloat16* kwT = wbf + 2*WU;
    __nv_bfloat16* vwT = wbf + 4*WU;
    __nv_bfloat16* oww = wbf + 6*WU;
    __nv_bfloat16* GT  = wbf + 8*WU;
    float* t_qwT = wf32 + 0*WU;
    float* t_kwT = wf32 + 1*WU;
    float* t_vwT = wf32 + 2*WU;
    float* t_GT  = wf32 + 3*WU;
    float* t_W2  = wf32 + 4*WU;

    __nv_bfloat16* embh_r = bf + 0*UU;
    __nv_bfloat16* embh_t = bf + 2*UU;
    float* emb_r = f32 + 0*UU;   // -> qg_r
    float* emb_t = f32 + 1*UU;   // -> qg_t
    float* lnf   = f32 + 2*UU;   // 2U
    float* valp  = f32 + 4*UU;   // 2U
    float* qg_r  = f32 + 0*UU;
    float* qg_t  = f32 + 1*UU;

    cudaFuncSetAttribute(tc_gemm, cudaFuncAttributeMaxDynamicSharedMemorySize, GEMM_SMEM);
    cudaFuncSetAttribute(tc_gemm_tf32, cudaFuncAttributeMaxDynamicSharedMemorySize, GEMM_SMEM);
    cudaFuncSetAttribute(attn_out_kernel, cudaFuncAttributeMaxDynamicSharedMemorySize, (int)ATTN_SMEM);

    dim3 g1(4, M1 / 128);     // (4, 288)
    dim3 g2(4, M2 / 128);     // (4, 576)
    dim3 gw(4, 8);
    dim3 gbn(M1, 2);
    dim3 gt(32, 32), bt(32, 8);

    // ---- weight preprocessing ----
    transpose_kernel<<<gt, bt>>>(q_w, t_qwT);
    transpose_kernel<<<gt, bt>>>(k_w, t_kwT);
    transpose_kernel<<<gt, bt>>>(v_w, t_vwT);
    cvt_kernel<<<(int)(WU/1024), 256>>>(t_qwT, qwT, qwT + WU);
    cvt_kernel<<<(int)(WU/1024), 256>>>(t_kwT, kwT, kwT + WU);
    cvt_kernel<<<(int)(WU/1024), 256>>>(t_vwT, vwT, vwT + WU);
    cvt_kernel<<<(int)(WU/1024), 256>>>(out_w, oww, oww + WU);
    tc_gemm<<<gw, 256, GEMM_SMEM>>>(kwT, WU, qwT, zeros, t_GT);   // GT = kw^T@qw
    tc_gemm<<<gw, 256, GEMM_SMEM>>>(oww, WU, vwT, zeros, t_W2);   // W2 = ow@vw
    cvt_kernel<<<(int)(WU/1024), 256>>>(t_GT, GT, GT + WU);
    uv_kernel<<<5, 256>>>(q_w, k_w, q_b, k_b);
    bias2_kernel<<<128, 256>>>(out_w, v_b);

    // ---- embedding GEMMs: tf32 directly on raw inputs ----
    tc_gemm_tf32<<<g1, 256, GEMM_SMEM>>>(attn_rgb, embed_w, embed_b, emb_r);
    tc_gemm_tf32<<<g1, 256, GEMM_SMEM>>>(attn_tir, embed_w, embed_b, emb_t);

    // ---- BatchNorm + pos -> emb bf16 hi/lo ----
    bn_zero_kernel<<<1, 32>>>();
    bn_stats_kernel<<<gbn, 256>>>(emb_r, emb_t);
    bn_finalize_kernel<<<1, 32>>>(bn_w, bn_b);
    bn_apply_cvt_kernel<<<gbn, 256>>>(emb_r, emb_t, pos_emb, embh_r, embh_t);

    // ---- LayerNorm (fp32) + value' GEMM (tf32, W2 fused) ----
    ln_kernel<<<M2, 256>>>(attn_rgb, attn_tir, ln_w, ln_b, lnf);
    tc_gemm_tf32<<<g2, 256, GEMM_SMEM>>>(lnf, t_W2, b2p, valp);

    // ---- dq/dk + qg projections (bf16x3) ----
    dqdk_kernel<<<gbn, 256>>>(embh_r, embh_t);
    tc_gemm<<<g1, 256, GEMM_SMEM>>>(embh_r, UU, GT, zeros, qg_r);
    tc_gemm<<<g1, 256, GEMM_SMEM>>>(embh_t, UU, GT, zeros, qg_t);

    // ---- attention + direct output ----
    attn_out_kernel<<<BH, 256, ATTN_SMEM>>>(qg_r, qg_t, embh_r, embh_t, valp, out_b, out);
}

// round 15
// speedup vs baseline: 3.4684x; 1.0380x over previous
#include <cuda_runtime.h>
#include <cuda_bf16.h>
#include <cstdint>
#include <cstddef>

#define BB   256
#define HN   12
#define N1   12
#define DD   1024
#define BH   (BB*HN)
#define M1   (BH*N1)         // 36864
#define M2   (BH*2*N1)       // 73728

#define UU   ((size_t)M1 * DD)
#define WU   ((size_t)DD * DD)

// ---------------------------------------------------------------------------
// Static scratch
// fp32 arena (6 U): 0..1: emb_r, emb_t (live through attn)
//                   2..3: lnf -> later qg_r, qg_t
//                   4..5: value'
// ---------------------------------------------------------------------------
__device__ float g_f32[6 * UU];
__device__ __nv_bfloat16 g_wbf[8 * WU];    // qwT h/l kwT h/l vwT h/l ow h/l
__device__ float g_wf32[5 * WU];           // t_qwT t_kwT t_vwT t_GT t_W2

__device__ float g_bn_sum[2][12];
__device__ float g_bn_sq [2][12];
__device__ float g_bn_scale[2][12];
__device__ float g_bn_shift[2][12];

__device__ float g_u[DD];
__device__ float g_v[DD];
__device__ float g_b2[DD];
__device__ float g_misc[4];
__device__ float g_zeros[DD];
__device__ float g_dq[2 * M1];
__device__ float g_dk[2 * M1];

// ---------------------------------------------------------------------------
// Helpers
// ---------------------------------------------------------------------------
__device__ __forceinline__ uint32_t smem_to_u32(const void* p) {
    uint32_t a;
    asm("{ .reg .u64 t; cvta.to.shared.u64 t, %1; cvt.u32.u64 %0, t; }" : "=r"(a) : "l"(p));
    return a;
}
__device__ __forceinline__ void cp16(uint32_t dst, const void* src) {
    asm volatile("cp.async.cg.shared.global [%0], [%1], 16;\n" :: "r"(dst), "l"(src));
}
__device__ __forceinline__ void cp_commit() {
    asm volatile("cp.async.commit_group;\n" ::: "memory");
}
__device__ __forceinline__ void ldsm4(uint32_t addr, uint32_t& r0, uint32_t& r1,
                                      uint32_t& r2, uint32_t& r3) {
    asm volatile("ldmatrix.sync.aligned.m8n8.x4.shared.b16 {%0,%1,%2,%3}, [%4];"
        : "=r"(r0), "=r"(r1), "=r"(r2), "=r"(r3) : "r"(addr));
}
__device__ __forceinline__ uint32_t lds_tf32(uint32_t addr) {
    float v;
    asm volatile("ld.shared.b32 %0, [%1];" : "=f"(v) : "r"(addr));
    uint32_t o;
    asm("cvt.rna.tf32.f32 %0, %1;" : "=r"(o) : "f"(v));
    return o;
}
__device__ __forceinline__ void mma16816(float* c, const uint32_t* a, uint32_t b0, uint32_t b1) {
    asm volatile("mma.sync.aligned.m16n8k16.row.col.f32.bf16.bf16.f32 "
        "{%0,%1,%2,%3}, {%4,%5,%6,%7}, {%8,%9}, {%0,%1,%2,%3};"
        : "+f"(c[0]), "+f"(c[1]), "+f"(c[2]), "+f"(c[3])
        : "r"(a[0]), "r"(a[1]), "r"(a[2]), "r"(a[3]), "r"(b0), "r"(b1));
}
__device__ __forceinline__ void mma1688t(float* c, const uint32_t* a, uint32_t b0, uint32_t b1) {
    asm volatile("mma.sync.aligned.m16n8k8.row.col.f32.tf32.tf32.f32 "
        "{%0,%1,%2,%3}, {%4,%5,%6,%7}, {%8,%9}, {%0,%1,%2,%3};"
        : "+f"(c[0]), "+f"(c[1]), "+f"(c[2]), "+f"(c[3])
        : "r"(a[0]), "r"(a[1]), "r"(a[2]), "r"(a[3]), "r"(b0), "r"(b1));
}

__device__ __forceinline__ uint32_t swz(int r, int s) {        // bf16 64B rows
    return (uint32_t)(r * 64 + ((s ^ ((r >> 1) & 3)) << 4));
}
__device__ __forceinline__ uint32_t swzt(int r, int s) {       // tf32 128B rows
    return (uint32_t)(r * 128 + ((s ^ (r & 7)) << 4));
}

__device__ __forceinline__ void split_bf16(float x, __nv_bfloat16& h, __nv_bfloat16& l) {
    h = __float2bfloat16(x);
    l = __float2bfloat16(x - __bfloat162float(h));
}

__global__ __launch_bounds__(256) void cvt_kernel(const float* __restrict__ x,
                                                  __nv_bfloat16* __restrict__ hi,
                                                  __nv_bfloat16* __restrict__ lo) {
    size_t idx = (size_t)blockIdx.x * 256 + threadIdx.x;
    float4 v = ((const float4*)x)[idx];
    __nv_bfloat16 h0,h1,h2,h3,l0,l1,l2,l3;
    split_bf16(v.x,h0,l0); split_bf16(v.y,h1,l1); split_bf16(v.z,h2,l2); split_bf16(v.w,h3,l3);
    __nv_bfloat162* hp = (__nv_bfloat162*)hi;
    __nv_bfloat162* lp = (__nv_bfloat162*)lo;
    hp[idx*2]   = {h0,h1}; hp[idx*2+1] = {h2,h3};
    lp[idx*2]   = {l0,l1}; lp[idx*2+1] = {l2,l3};
}

// 3 transposes in one launch (blockIdx.z selects)
__global__ void transpose3_kernel(const float* q, const float* k, const float* v,
                                  float* dq, float* dk, float* dv) {
    __shared__ float t[32][33];
    const float* src; float* dst;
    if (blockIdx.z == 0)      { src = q; dst = dq; }
    else if (blockIdx.z == 1) { src = k; dst = dk; }
    else                      { src = v; dst = dv; }
    int x = blockIdx.x * 32 + threadIdx.x;
    int y = blockIdx.y * 32 + threadIdx.y;
    #pragma unroll
    for (int r = 0; r < 4; r++)
        t[threadIdx.y + r * 8][threadIdx.x] = src[(size_t)(y + r * 8) * DD + x];
    __syncthreads();
    int x2 = blockIdx.y * 32 + threadIdx.x;
    int y2 = blockIdx.x * 32 + threadIdx.y;
    #pragma unroll
    for (int r = 0; r < 4; r++)
        dst[(size_t)(y2 + r * 8) * DD + x2] = t[threadIdx.x][threadIdx.y + r * 8];
}

// ---------------------------------------------------------------------------
// bf16x3 GEMM (weight prep only): C = A@W^T. A hi/lo (+loD), W hi/lo (+WU).
// BM=128 BN=256 BK=32, 256 thr, 8 warps 2x4.
// ---------------------------------------------------------------------------
#define STAGE_BYTES 49152
#define GEMM_SMEM   (2 * STAGE_BYTES)

__global__ __launch_bounds__(256, 1) void tc_gemm(
    const __nv_bfloat16* __restrict__ A0h, size_t loD,
    const __nv_bfloat16* __restrict__ Wh,
    const float* __restrict__ bias, float* __restrict__ C)
{
    extern __shared__ char smem[];
    const uint32_t sb = smem_to_u32(smem);
    const int tid = threadIdx.x;
    const int bm = blockIdx.y * 128;
    const int bn = blockIdx.x * 256;

    const int lr = tid >> 1;
    const int s0 = (tid & 1) * 2;
    const char* aP = (const char*)(A0h + (size_t)(bm + lr) * DD);
    const char* wP = (const char*)(Wh + (size_t)(bn + tid) * DD);
    const size_t loB  = loD * 2;
    const size_t wLoB = WU * 2;

    const uint32_t aD0 = swz(lr, s0);
    const uint32_t aD1 = swz(lr, s0 + 1);
    uint32_t wD[4];
    #pragma unroll
    for (int j = 0; j < 4; j++) wD[j] = swz(tid, j);

    const int wid = tid >> 5, lane = tid & 31;
    const int wm = wid & 1, wn = wid >> 1;
    const int rowA = wm * 64 + (lane & 15);
    const int segA = lane >> 4;
    const int xA = (rowA >> 1) & 3;
    const uint32_t aRowOff = rowA * 64;
    uint32_t aCol[2];
    aCol[0] = (uint32_t)(((segA + 0) ^ xA) << 4);
    aCol[1] = (uint32_t)(((segA + 2) ^ xA) << 4);
    const int rowB = wn * 64 + (lane & 7) + ((lane >> 4) << 3);
    const int segB = (lane >> 3) & 1;
    const int xB = (rowB >> 1) & 3;
    const uint32_t bRowOff = rowB * 64;
    uint32_t bCol[2];
    bCol[0] = (uint32_t)(((segB + 0) ^ xB) << 4);
    bCol[1] = (uint32_t)(((segB + 2) ^ xB) << 4);

    float acc[4][8][4];
    #pragma unroll
    for (int i = 0; i < 4; i++)
        #pragma unroll
        for (int j = 0; j < 8; j++)
            #pragma unroll
            for (int t = 0; t < 4; t++) acc[i][j][t] = 0.f;

    auto load_stage = [&](int c, int st) {
        uint32_t B = sb + st * STAGE_BYTES;
        size_t off = (size_t)c * 64;
        cp16(B + aD0,        aP + off + s0 * 16);
        cp16(B + aD1,        aP + off + s0 * 16 + 16);
        cp16(B + 8192 + aD0, aP + loB + off + s0 * 16);
        cp16(B + 8192 + aD1, aP + loB + off + s0 * 16 + 16);
        #pragma unroll
        for (int j = 0; j < 4; j++) {
            cp16(B + 16384 + wD[j], wP + off + j * 16);
            cp16(B + 32768 + wD[j], wP + wLoB + off + j * 16);
        }
        cp_commit();
    };

    auto do_mmas = [&](uint32_t a[4][4], uint32_t b[4][4]) {
        #pragma unroll
        for (int mi = 0; mi < 4; mi++)
            #pragma unroll
            for (int p = 0; p < 4; p++) {
                mma16816(acc[mi][2*p],   a[mi], b[p][0], b[p][1]);
                mma16816(acc[mi][2*p+1], a[mi], b[p][2], b[p][3]);
            }
    };

    auto compute_stage = [&](int st) {
        uint32_t base = sb + st * STAGE_BYTES;
        uint32_t aH = base + aRowOff;
        uint32_t aL = aH + 8192;
        uint32_t bH = base + 16384 + bRowOff;
        uint32_t bL = bH + 16384;
        #pragma unroll
        for (int k = 0; k < 2; k++) {
            uint32_t a[4][4], b[4][4];
            #pragma unroll
            for (int p = 0; p < 4; p++)
                ldsm4(bH + p * 1024 + bCol[k], b[p][0], b[p][1], b[p][2], b[p][3]);
            #pragma unroll
            for (int mi = 0; mi < 4; mi++)
                ldsm4(aH + mi * 1024 + aCol[k], a[mi][0], a[mi][1], a[mi][2], a[mi][3]);
            do_mmas(a, b);
            #pragma unroll
            for (int mi = 0; mi < 4; mi++)
                ldsm4(aL + mi * 1024 + aCol[k], a[mi][0], a[mi][1], a[mi][2], a[mi][3]);
            do_mmas(a, b);
            #pragma unroll
            for (int p = 0; p < 4; p++)
                ldsm4(bL + p * 1024 + bCol[k], b[p][0], b[p][1], b[p][2], b[p][3]);
            #pragma unroll
            for (int mi = 0; mi < 4; mi++)
                ldsm4(aH + mi * 1024 + aCol[k], a[mi][0], a[mi][1], a[mi][2], a[mi][3]);
            do_mmas(a, b);
        }
    };

    load_stage(0, 0);
    #pragma unroll 1
    for (int c = 0; c < 32; c++) {
        int st = c & 1;
        if (c + 1 < 32) {
            load_stage(c + 1, st ^ 1);
            asm volatile("cp.async.wait_group 1;" ::: "memory");
        } else {
            asm volatile("cp.async.wait_group 0;" ::: "memory");
        }
        __syncthreads();
        compute_stage(st);
        __syncthreads();
    }

    const int r0   = bm + wm * 64 + (lane >> 2);
    const int col0 = bn + wn * 64 + (lane & 3) * 2;
    #pragma unroll
    for (int nf = 0; nf < 8; nf++) {
        int col = col0 + nf * 8;
        float bx = bias[col], by = bias[col + 1];
        #pragma unroll
        for (int mi = 0; mi < 4; mi++) {
            float* p0 = C + (size_t)(r0 + mi * 16) * DD + col;
            float2 v0 = { acc[mi][nf][0] + bx, acc[mi][nf][1] + by };
            float2 v1 = { acc[mi][nf][2] + bx, acc[mi][nf][3] + by };
            *(float2*)p0 = v0;
            *(float2*)(p0 + 8 * DD) = v1;
        }
    }
}

// ---------------------------------------------------------------------------
// tf32 single-term GEMM, z-batched: C[z] = A[z]@W^T + bias.
// ---------------------------------------------------------------------------
__global__ __launch_bounds__(256, 1) void tc_gemm_tf32(
    const float* __restrict__ A0, const float* __restrict__ A1,
    const float* __restrict__ W,
    const float* __restrict__ bias,
    float* __restrict__ C0, float* __restrict__ C1)
{
    extern __shared__ char smem[];
    const uint32_t sb = smem_to_u32(smem);
    const int tid = threadIdx.x;
    const int bm = blockIdx.y * 128;
    const int bn = blockIdx.x * 256;
    const float* A = blockIdx.z ? A1 : A0;
    float* C = blockIdx.z ? C1 : C0;

    const int lr = tid >> 1;
    const int s0 = (tid & 1) * 4;
    const char* aP = (const char*)(A + (size_t)(bm + lr) * DD);
    const char* wP = (const char*)(W + (size_t)(bn + tid) * DD);
    uint32_t aD[4], wD[8];
    #pragma unroll
    for (int j = 0; j < 4; j++) aD[j] = swzt(lr, s0 + j);
    #pragma unroll
    for (int j = 0; j < 8; j++) wD[j] = swzt(tid, j);

    const int wid = tid >> 5, lane = tid & 31;
    const int wm = wid & 1, wn = wid >> 1;
    const int tR = lane >> 2;
    const uint32_t tC4 = (uint32_t)((lane & 3) * 4);

    float acc[4][8][4];
    #pragma unroll
    for (int i = 0; i < 4; i++)
        #pragma unroll
        for (int j = 0; j < 8; j++)
            #pragma unroll
            for (int t = 0; t < 4; t++) acc[i][j][t] = 0.f;

    auto load_stage = [&](int c, int st) {
        uint32_t B = sb + st * STAGE_BYTES;
        size_t off = (size_t)c * 128;
        #pragma unroll
        for (int j = 0; j < 4; j++)
            cp16(B + aD[j], aP + off + (s0 + j) * 16);
        #pragma unroll
        for (int j = 0; j < 8; j++)
            cp16(B + 16384 + wD[j], wP + off + j * 16);
        cp_commit();
    };

    auto compute_stage = [&](int st) {
        uint32_t base = sb + st * STAGE_BYTES;
        #pragma unroll
        for (int k8 = 0; k8 < 4; k8++) {
            uint32_t bF[8][2], aF[4][4];
            #pragma unroll
            for (int nf = 0; nf < 8; nf++) {
                int n = wn * 64 + nf * 8 + tR;
                uint32_t nb = base + 16384 + n * 128 + tC4;
                bF[nf][0] = lds_tf32(nb + (((k8*2)     ^ (n & 7)) << 4));
                bF[nf][1] = lds_tf32(nb + (((k8*2 + 1) ^ (n & 7)) << 4));
            }
            #pragma unroll
            for (int mi = 0; mi < 4; mi++) {
                #pragma unroll
                for (int h = 0; h < 2; h++) {
                    int r = wm * 64 + mi * 16 + h * 8 + tR;
                    uint32_t rb = base + r * 128 + tC4;
                    aF[mi][h]     = lds_tf32(rb + (((k8*2)     ^ (r & 7)) << 4));
                    aF[mi][h + 2] = lds_tf32(rb + (((k8*2 + 1) ^ (r & 7)) << 4));
                }
            }
            #pragma unroll
            for (int mi = 0; mi < 4; mi++)
                #pragma unroll
                for (int nf = 0; nf < 8; nf++)
                    mma1688t(acc[mi][nf], aF[mi], bF[nf][0], bF[nf][1]);
        }
    };

    load_stage(0, 0);
    #pragma unroll 1
    for (int c = 0; c < 32; c++) {
        int st = c & 1;
        if (c + 1 < 32) {
            load_stage(c + 1, st ^ 1);
            asm volatile("cp.async.wait_group 1;" ::: "memory");
        } else {
            asm volatile("cp.async.wait_group 0;" ::: "memory");
        }
        __syncthreads();
        compute_stage(st);
        __syncthreads();
    }

    const int r0   = bm + wm * 64 + (lane >> 2);
    const int col0 = bn + wn * 64 + (lane & 3) * 2;
    #pragma unroll
    for (int nf = 0; nf < 8; nf++) {
        int col = col0 + nf * 8;
        float bx = bias[col], by = bias[col + 1];
        #pragma unroll
        for (int mi = 0; mi < 4; mi++) {
            float* p0 = C + (size_t)(r0 + mi * 16) * DD + col;
            float2 v0 = { acc[mi][nf][0] + bx, acc[mi][nf][1] + by };
            float2 v1 = { acc[mi][nf][2] + bx, acc[mi][nf][3] + by };
            *(float2*)p0 = v0;
            *(float2*)(p0 + 8 * DD) = v1;
        }
    }
}

// ---------------------------------------------------------------------------
// Bias algebra
// ---------------------------------------------------------------------------
__global__ __launch_bounds__(256) void uv_kernel(const float* __restrict__ qw,
                                                 const float* __restrict__ kw,
                                                 const float* __restrict__ qb,
                                                 const float* __restrict__ kb) {
    if (blockIdx.x < 4) {
        int d = blockIdx.x * 256 + threadIdx.x;
        float su = 0.f, sv = 0.f;
        for (int c = 0; c < DD; c++) {
            su += qw[(size_t)c * DD + d] * kb[c];
            sv += kw[(size_t)c * DD + d] * qb[c];
        }
        g_u[d] = su;
        g_v[d] = sv;
    } else {
        int tid = threadIdx.x;
        float s = qb[tid]*kb[tid] + qb[tid+256]*kb[tid+256]
                + qb[tid+512]*kb[tid+512] + qb[tid+768]*kb[tid+768];
        #pragma unroll
        for (int o = 16; o > 0; o >>= 1) s += __shfl_xor_sync(~0u, s, o);
        __shared__ float ss[8];
        if ((tid & 31) == 0) ss[tid >> 5] = s;
        __syncthreads();
        if (tid == 0) {
            float S = 0.f;
            #pragma unroll
            for (int w = 0; w < 8; w++) S += ss[w];
            g_misc[0] = S;
        }
    }
}

__global__ __launch_bounds__(256) void bias2_kernel(const float* __restrict__ ow,
                                                    const float* __restrict__ vb) {
    int wid = threadIdx.x >> 5, lane = threadIdx.x & 31;
    int row = blockIdx.x * 8 + wid;
    const float* r = ow + (size_t)row * DD;
    float s = 0.f;
    for (int c = lane; c < DD; c += 32) s += r[c] * vb[c];
    #pragma unroll
    for (int o = 16; o > 0; o >>= 1) s += __shfl_xor_sync(~0u, s, o);
    if (lane == 0) g_b2[row] = s;
}

// dq/dk from fp32 emb_norm
__global__ __launch_bounds__(256) void dqdk_kernel(const float* __restrict__ x0,
                                                   const float* __restrict__ x1) {
    int row = blockIdx.x, sidx = blockIdx.y, tid = threadIdx.x;
    const float* x = sidx ? x1 : x0;
    float4 v = ((const float4*)(x + (size_t)row * DD))[tid];
    float4 u4 = ((const float4*)g_u)[tid];
    float4 v4 = ((const float4*)g_v)[tid];
    float su = v.x*u4.x + v.y*u4.y + v.z*u4.z + v.w*u4.w;
    float sv = v.x*v4.x + v.y*v4.y + v.z*v4.z + v.w*v4.w;
    #pragma unroll
    for (int o = 16; o > 0; o >>= 1) {
        su += __shfl_xor_sync(~0u, su, o);
        sv += __shfl_xor_sync(~0u, sv, o);
    }
    __shared__ float ssu[8], ssv[8];
    if ((tid & 31) == 0) { ssu[tid >> 5] = su; ssv[tid >> 5] = sv; }
    __syncthreads();
    if (tid == 0) {
        float SU = 0.f, SV = 0.f;
        #pragma unroll
        for (int w = 0; w < 8; w++) { SU += ssu[w]; SV += ssv[w]; }
        g_dq[sidx * M1 + row] = SU;
        g_dk[sidx * M1 + row] = SV;
    }
}

// ---------------------------------------------------------------------------
// BatchNorm
// ---------------------------------------------------------------------------
__global__ void bn_zero_kernel() {
    int t = threadIdx.x;
    if (t < 24) { ((float*)g_bn_sum)[t] = 0.f; ((float*)g_bn_sq)[t] = 0.f; }
}

__global__ __launch_bounds__(256) void bn_stats_kernel(const float* __restrict__ x0,
                                                       const float* __restrict__ x1) {
    int row  = blockIdx.x;
    int sidx = blockIdx.y;
    int tid  = threadIdx.x;
    const float* x = sidx ? x1 : x0;
    float4 v = ((const float4*)(x + (size_t)row * DD))[tid];
    float s = v.x + v.y + v.z + v.w;
    float q = v.x*v.x + v.y*v.y + v.z*v.z + v.w*v.w;
    #pragma unroll
    for (int o = 16; o > 0; o >>= 1) {
        s += __shfl_xor_sync(~0u, s, o);
        q += __shfl_xor_sync(~0u, q, o);
    }
    __shared__ float ss[8], qq[8];
    if ((tid & 31) == 0) { ss[tid >> 5] = s; qq[tid >> 5] = q; }
    __syncthreads();
    if (tid == 0) {
        float S = 0.f, Q = 0.f;
        #pragma unroll
        for (int w = 0; w < 8; w++) { S += ss[w]; Q += qq[w]; }
        atomicAdd(&g_bn_sum[sidx][row % 12], S);
        atomicAdd(&g_bn_sq [sidx][row % 12], Q);
    }
}

__global__ void bn_finalize_kernel(const float* __restrict__ bn_w, const float* __restrict__ bn_b) {
    int t = threadIdx.x;
    if (t < 24) {
        int s = t / 12, c = t % 12;
        const float CNT = 3072.0f * 1024.0f;
        float mean = g_bn_sum[s][c] / CNT;
        float var  = g_bn_sq [s][c] / CNT - mean * mean;
        float rstd = rsqrtf(var + 1e-5f);
        float sc   = rstd * bn_w[c];
        g_bn_scale[s][c] = sc;
        g_bn_shift[s][c] = bn_b[c] - mean * sc;
    }
}

// in-place fp32: x = x*scale_c + shift_c + pos
__global__ __launch_bounds__(256) void bn_apply_kernel(float* __restrict__ x0,
                                                       float* __restrict__ x1,
                                                       const float* __restrict__ pos) {
    int row  = blockIdx.x;
    int sidx = blockIdx.y;
    int tid  = threadIdx.x;
    float* x = sidx ? x1 : x0;
    int c = row % 12;
    int b = row / 144;
    float sc = g_bn_scale[sidx][c], sh = g_bn_shift[sidx][c];
    float4 p = ((const float4*)(pos + ((size_t)(b * 12 + c)) * DD))[tid];
    float4* xp = (float4*)(x + (size_t)row * DD) + tid;
    float4 v = *xp;
    v.x = v.x * sc + sh + p.x;
    v.y = v.y * sc + sh + p.y;
    v.z = v.z * sc + sh + p.z;
    v.w = v.w * sc + sh + p.w;
    *xp = v;
}

// ---------------------------------------------------------------------------
// LayerNorm of concat(ar, at) -> fp32
// ---------------------------------------------------------------------------
__global__ __launch_bounds__(256) void ln_kernel(const float* __restrict__ ar,
                                                 const float* __restrict__ at,
                                                 const float* __restrict__ lnw,
                                                 const float* __restrict__ lnb,
                                                 float* __restrict__ out) {
    int row = blockIdx.x;
    int tid = threadIdx.x;
    int bh = row / 24, j = row % 24;
    const float* src = (j < 12) ? ar + ((size_t)bh * 12 + j) * DD
                                : at + ((size_t)bh * 12 + (j - 12)) * DD;
    float4 v = ((const float4*)src)[tid];
    float s = v.x + v.y + v.z + v.w;
    float q = v.x*v.x + v.y*v.y + v.z*v.z + v.w*v.w;
    #pragma unroll
    for (int o = 16; o > 0; o >>= 1) {
        s += __shfl_xor_sync(~0u, s, o);
        q += __shfl_xor_sync(~0u, q, o);
    }
    __shared__ float ss[8], qq[8], mom[2];
    if ((tid & 31) == 0) { ss[tid >> 5] = s; qq[tid >> 5] = q; }
    __syncthreads();
    if (tid == 0) {
        float S = 0.f, Q = 0.f;
        #pragma unroll
        for (int w = 0; w < 8; w++) { S += ss[w]; Q += qq[w]; }
        float mean = S / 1024.0f;
        float var  = Q / 1024.0f - mean * mean;
        mom[0] = mean;
        mom[1] = rsqrtf(var + 1e-5f);
    }
    __syncthreads();
    float mean = mom[0], rstd = mom[1];
    float4 w = ((const float4*)lnw)[tid];
    float4 bb = ((const float4*)lnb)[tid];
    float4 o4;
    o4.x = (v.x - mean) * rstd * w.x + bb.x;
    o4.y = (v.y - mean) * rstd * w.y + bb.y;
    o4.z = (v.z - mean) * rstd * w.z + bb.z;
    o4.w = (v.w - mean) * rstd * w.w + bb.w;
    ((float4*)(out + (size_t)row * DD))[tid] = o4;
}

// ---------------------------------------------------------------------------
// Fused attention + output (all fp32 inputs)
// ---------------------------------------------------------------------------
#define ATTN_SMEM ((24*1024 + 24*24 + 32) * sizeof(float))

__global__ __launch_bounds__(256) void attn_out_kernel(
    const float* __restrict__ qg_r, const float* __restrict__ qg_t,
    const float* __restrict__ x_r, const float* __restrict__ x_t,
    const float* __restrict__ valp,
    const float* __restrict__ ob,
    float* __restrict__ out) {
    extern __shared__ float sm[];
    float* xs  = sm;
    float* at  = sm + 24 * 1024;
    float* dks = at + 24 * 24;

    int bh  = blockIdx.x;
    int tid = threadIdx.x;
    int warp = tid >> 5, lane = tid & 31;

    // stage x = emb_norm concat (fp32)
    const float* xr = x_r + (size_t)bh * 12 * DD;
    const float* xt = x_t + (size_t)bh * 12 * DD;
    for (int i = tid; i < 12 * 256; i += 256) {
        ((float4*)xs)[i]            = ((const float4*)xr)[i];
        ((float4*)xs)[i + 12 * 256] = ((const float4*)xt)[i];
    }
    if (tid < 24) {
        int s = tid < 12 ? 0 : 1;
        dks[tid] = g_dk[s * M1 + bh * 12 + (tid % 12)];
    }
    __syncthreads();

    float c0v = g_misc[0];

    for (int qi = warp * 3; qi < warp * 3 + 3; qi++) {
        int s = (qi < 12) ? 0 : 1;
        const float* qrow = (s ? qg_t : qg_r) + ((size_t)bh * 12 + (qi % 12)) * DD;
        float dqv = g_dq[s * M1 + bh * 12 + (qi % 12)];
        float qv[32];
        #pragma unroll
        for (int t = 0; t < 32; t++) qv[t] = qrow[t * 32 + lane];
        for (int j = 0; j < 24; j++) {
            float sum = 0.f;
            #pragma unroll
            for (int t = 0; t < 32; t++) sum += qv[t] * xs[j * 1024 + t * 32 + lane];
            #pragma unroll
            for (int o = 16; o > 0; o >>= 1) sum += __shfl_xor_sync(~0u, sum, o);
            if (lane == 0) at[qi * 24 + j] = (sum + dqv + dks[j] + c0v) * 0.03125f;
        }
    }
    __syncthreads();

    for (int qi = warp * 3; qi < warp * 3 + 3; qi++) {
        float v = (lane < 24) ? at[qi * 24 + lane] : -3.0e38f;
        float m = v;
        #pragma unroll
        for (int o = 16; o > 0; o >>= 1) m = fmaxf(m, __shfl_xor_sync(~0u, m, o));
        float e = (lane < 24) ? expf(v - m) : 0.f;
        float s = e;
        #pragma unroll
        for (int o = 16; o > 0; o >>= 1) s += __shfl_xor_sync(~0u, s, o);
        if (lane < 24) at[qi * 24 + lane] = e / s;
    }
    __syncthreads();

    const float* vbase = valp + (size_t)bh * 24 * DD;
    for (int i = tid; i < 24 * 256; i += 256)
        ((float4*)xs)[i] = ((const float4*)vbase)[i];
    __syncthreads();

    int c0l = tid * 4;
    float4 obv = *(const float4*)(ob + c0l);
    for (int i = 0; i < 24; i++) {
        float4 acc = obv;
        #pragma unroll
        for (int j = 0; j < 24; j++) {
            float a = at[i * 24 + j];
            float4 v4 = *(const float4*)&xs[j * 1024 + c0l];
            acc.x += a * v4.x; acc.y += a * v4.y; acc.z += a * v4.z; acc.w += a * v4.w;
        }
        float* dst = out + ((i < 12) ? 0 : (size_t)M1 * DD)
                   + ((size_t)bh * 12 + (i % 12)) * DD + c0l;
        *(float4*)dst = acc;
    }
}

// ---------------------------------------------------------------------------
// Launch
// ---------------------------------------------------------------------------
extern "C" void kernel_launch(void* const* d_in, const int* in_sizes, int n_in,
                              void* d_out, int out_size) {
    const float* attn_rgb = (const float*)d_in[0];
    const float* attn_tir = (const float*)d_in[1];
    const float* pos_emb  = (const float*)d_in[2];
    const float* embed_w  = (const float*)d_in[3];
    const float* embed_b  = (const float*)d_in[4];
    const float* bn_w     = (const float*)d_in[5];
    const float* bn_b     = (const float*)d_in[6];
    const float* ln_w     = (const float*)d_in[7];
    const float* ln_b     = (const float*)d_in[8];
    const float* v_w      = (const float*)d_in[9];
    const float* v_b      = (const float*)d_in[10];
    const float* q_w      = (const float*)d_in[11];
    const float* q_b      = (const float*)d_in[12];
    const float* k_w      = (const float*)d_in[13];
    const float* k_b      = (const float*)d_in[14];
    const float* out_w    = (const float*)d_in[15];
    const float* out_b    = (const float*)d_in[16];
    float* out = (float*)d_out;

    __nv_bfloat16* wbf;
    float *f32, *wf32, *zeros, *b2p;
    cudaGetSymbolAddress((void**)&wbf,   g_wbf);
    cudaGetSymbolAddress((void**)&f32,   g_f32);
    cudaGetSymbolAddress((void**)&wf32,  g_wf32);
    cudaGetSymbolAddress((void**)&zeros, g_zeros);
    cudaGetSymbolAddress((void**)&b2p,   g_b2);

    __nv_bfloat16* qwT = wbf + 0*WU;   // hi; lo at +WU
    __nv_bfloat16* kwT = wbf + 2*WU;
    __nv_bfloat16* vwT = wbf + 4*WU;
    __nv_bfloat16* oww = wbf + 6*WU;
    float* t_qwT = wf32 + 0*WU;
    float* t_kwT = wf32 + 1*WU;
    float* t_vwT = wf32 + 2*WU;
    float* t_GT  = wf32 + 3*WU;
    float* t_W2  = wf32 + 4*WU;

    float* emb_r = f32 + 0*UU;
    float* emb_t = f32 + 1*UU;
    float* lnf   = f32 + 2*UU;   // 2U; -> qg after value GEMM
    float* valp  = f32 + 4*UU;   // 2U
    float* qg_r  = f32 + 2*UU;
    float* qg_t  = f32 + 3*UU;

    cudaFuncSetAttribute(tc_gemm, cudaFuncAttributeMaxDynamicSharedMemorySize, GEMM_SMEM);
    cudaFuncSetAttribute(tc_gemm_tf32, cudaFuncAttributeMaxDynamicSharedMemorySize, GEMM_SMEM);
    cudaFuncSetAttribute(attn_out_kernel, cudaFuncAttributeMaxDynamicSharedMemorySize, (int)ATTN_SMEM);

    dim3 g1z(4, M1 / 128, 2);  // batched pair (embed, qg)
    dim3 g2(4, M2 / 128, 1);   // value
    dim3 gw(4, 8);
    dim3 gbn(M1, 2);
    dim3 gt(32, 32, 3), bt(32, 8);

    // ---- weight preprocessing ----
    transpose3_kernel<<<gt, bt>>>(q_w, k_w, v_w, t_qwT, t_kwT, t_vwT);
    cvt_kernel<<<(int)(WU/1024), 256>>>(t_qwT, qwT, qwT + WU);
    cvt_kernel<<<(int)(WU/1024), 256>>>(t_kwT, kwT, kwT + WU);
    cvt_kernel<<<(int)(WU/1024), 256>>>(t_vwT, vwT, vwT + WU);
    cvt_kernel<<<(int)(WU/1024), 256>>>(out_w, oww, oww + WU);
    tc_gemm<<<gw, 256, GEMM_SMEM>>>(kwT, WU, qwT, zeros, t_GT);   // GT = kw^T@qw
    tc_gemm<<<gw, 256, GEMM_SMEM>>>(oww, WU, vwT, zeros, t_W2);   // W2 = ow@vw
    uv_kernel<<<5, 256>>>(q_w, k_w, q_b, k_b);
    bias2_kernel<<<128, 256>>>(out_w, v_b);

    // ---- embedding GEMMs (tf32, z-batched) ----
    tc_gemm_tf32<<<g1z, 256, GEMM_SMEM>>>(attn_rgb, attn_tir, embed_w, embed_b, emb_r, emb_t);

    // ---- BatchNorm + pos (in-place fp32) ----
    bn_zero_kernel<<<1, 32>>>();
    bn_stats_kernel<<<gbn, 256>>>(emb_r, emb_t);
    bn_finalize_kernel<<<1, 32>>>(bn_w, bn_b);
    bn_apply_kernel<<<gbn, 256>>>(emb_r, emb_t, pos_emb);

    // ---- LayerNorm + value' GEMM (tf32, W2 fused) ----
    ln_kernel<<<M2, 256>>>(attn_rgb, attn_tir, ln_w, ln_b, lnf);
    tc_gemm_tf32<<<g2, 256, GEMM_SMEM>>>(lnf, nullptr, t_W2, b2p, valp, nullptr);

    // ---- dq/dk + qg projections (tf32, z-batched; writes over dead lnf) ----
    dqdk_kernel<<<gbn, 256>>>(emb_r, emb_t);
    tc_gemm_tf32<<<g1z, 256, GEMM_SMEM>>>(emb_r, emb_t, t_GT, zeros, qg_r, qg_t);

    // ---- attention + direct output ----
    attn_out_kernel<<<BH, 256, ATTN_SMEM>>>(qg_r, qg_t, emb_r, emb_t, valp, out_b, out);
}

// round 16
// speedup vs baseline: 3.6109x; 1.0411x over previous
#include <cuda_runtime.h>
#include <cuda_bf16.h>
#include <cstdint>
#include <cstddef>

#define BB   256
#define HN   12
#define N1   12
#define DD   1024
#define BH   (BB*HN)
#define M1   (BH*N1)         // 36864
#define M2   (BH*2*N1)       // 73728

#define UU   ((size_t)M1 * DD)
#define WU   ((size_t)DD * DD)

// ---------------------------------------------------------------------------
// Static scratch
// fp32 arena (6 U): 0..1 emb_r, emb_t | 2..3 qg_r, qg_t | 4..5 value'
// ---------------------------------------------------------------------------
__device__ float g_f32[6 * UU];
__device__ __nv_bfloat16 g_wbf[8 * WU];    // qwT h/l kwT h/l vwTL h/l ow h/l
__device__ float g_wf32[5 * WU];           // t_qwT t_kwT t_vwT t_GT t_W2L

__device__ float g_bn_sum[2][12];
__device__ float g_bn_sq [2][12];
__device__ float g_bn_scale[2][12];
__device__ float g_bn_shift[2][12];

__device__ float g_u[DD];
__device__ float g_v[DD];
__device__ float g_t1[DD];
__device__ float g_t2[DD];
__device__ float g_wl2[DD];
__device__ float g_b2t[DD];
__device__ float g_misc[4];
__device__ float g_zeros[DD];
__device__ float g_dq[2 * M1];
__device__ float g_dk[2 * M1];
__device__ float g_s1[M2];     // rstd per concat row
__device__ float g_s2[M2];     // -mu*rstd per concat row

// ---------------------------------------------------------------------------
// Helpers
// ---------------------------------------------------------------------------
__device__ __forceinline__ uint32_t smem_to_u32(const void* p) {
    uint32_t a;
    asm("{ .reg .u64 t; cvta.to.shared.u64 t, %1; cvt.u32.u64 %0, t; }" : "=r"(a) : "l"(p));
    return a;
}
__device__ __forceinline__ void cp16(uint32_t dst, const void* src) {
    asm volatile("cp.async.cg.shared.global [%0], [%1], 16;\n" :: "r"(dst), "l"(src));
}
__device__ __forceinline__ void cp_commit() {
    asm volatile("cp.async.commit_group;\n" ::: "memory");
}
__device__ __forceinline__ void ldsm4(uint32_t addr, uint32_t& r0, uint32_t& r1,
                                      uint32_t& r2, uint32_t& r3) {
    asm volatile("ldmatrix.sync.aligned.m8n8.x4.shared.b16 {%0,%1,%2,%3}, [%4];"
        : "=r"(r0), "=r"(r1), "=r"(r2), "=r"(r3) : "r"(addr));
}
__device__ __forceinline__ uint32_t lds_tf32(uint32_t addr) {
    float v;
    asm volatile("ld.shared.b32 %0, [%1];" : "=f"(v) : "r"(addr));
    uint32_t o;
    asm("cvt.rna.tf32.f32 %0, %1;" : "=r"(o) : "f"(v));
    return o;
}
__device__ __forceinline__ void mma16816(float* c, const uint32_t* a, uint32_t b0, uint32_t b1) {
    asm volatile("mma.sync.aligned.m16n8k16.row.col.f32.bf16.bf16.f32 "
        "{%0,%1,%2,%3}, {%4,%5,%6,%7}, {%8,%9}, {%0,%1,%2,%3};"
        : "+f"(c[0]), "+f"(c[1]), "+f"(c[2]), "+f"(c[3])
        : "r"(a[0]), "r"(a[1]), "r"(a[2]), "r"(a[3]), "r"(b0), "r"(b1));
}
__device__ __forceinline__ void mma1688t(float* c, const uint32_t* a, uint32_t b0, uint32_t b1) {
    asm volatile("mma.sync.aligned.m16n8k8.row.col.f32.tf32.tf32.f32 "
        "{%0,%1,%2,%3}, {%4,%5,%6,%7}, {%8,%9}, {%0,%1,%2,%3};"
        : "+f"(c[0]), "+f"(c[1]), "+f"(c[2]), "+f"(c[3])
        : "r"(a[0]), "r"(a[1]), "r"(a[2]), "r"(a[3]), "r"(b0), "r"(b1));
}

__device__ __forceinline__ uint32_t swz(int r, int s) {        // bf16 64B rows
    return (uint32_t)(r * 64 + ((s ^ ((r >> 1) & 3)) << 4));
}
__device__ __forceinline__ uint32_t swzt(int r, int s) {       // tf32 128B rows
    return (uint32_t)(r * 128 + ((s ^ (r & 7)) << 4));
}

__device__ __forceinline__ void split_bf16(float x, __nv_bfloat16& h, __nv_bfloat16& l) {
    h = __float2bfloat16(x);
    l = __float2bfloat16(x - __bfloat162float(h));
}

// 4 weight splits in one launch. z=2 applies per-row scale (lnw) before split.
__global__ __launch_bounds__(256) void wcvt4_kernel(
    const float* s0, const float* s1, const float* s2, const float* s3,
    const float* __restrict__ rowscale,
    __nv_bfloat16* d0, __nv_bfloat16* d1, __nv_bfloat16* d2, __nv_bfloat16* d3) {
    const float* s; __nv_bfloat16* d; bool sc = false;
    switch (blockIdx.y) {
        case 0: s = s0; d = d0; break;
        case 1: s = s1; d = d1; break;
        case 2: s = s2; d = d2; sc = true; break;
        default: s = s3; d = d3; break;
    }
    size_t idx = (size_t)blockIdx.x * 256 + threadIdx.x;
    float4 v = ((const float4*)s)[idx];
    if (sc) {
        float f = rowscale[idx >> 8];    // row = (idx*4)/1024
        v.x *= f; v.y *= f; v.z *= f; v.w *= f;
    }
    __nv_bfloat16 h0,h1,h2,h3,l0,l1,l2,l3;
    split_bf16(v.x,h0,l0); split_bf16(v.y,h1,l1); split_bf16(v.z,h2,l2); split_bf16(v.w,h3,l3);
    __nv_bfloat162* hp = (__nv_bfloat162*)d;
    __nv_bfloat162* lp = (__nv_bfloat162*)(d + WU);
    hp[idx*2]   = {h0,h1}; hp[idx*2+1] = {h2,h3};
    lp[idx*2]   = {l0,l1}; lp[idx*2+1] = {l2,l3};
}

// 3 transposes in one launch (blockIdx.z selects)
__global__ void transpose3_kernel(const float* q, const float* k, const float* v,
                                  float* dq, float* dk, float* dv) {
    __shared__ float t[32][33];
    const float* src; float* dst;
    if (blockIdx.z == 0)      { src = q; dst = dq; }
    else if (blockIdx.z == 1) { src = k; dst = dk; }
    else                      { src = v; dst = dv; }
    int x = blockIdx.x * 32 + threadIdx.x;
    int y = blockIdx.y * 32 + threadIdx.y;
    #pragma unroll
    for (int r = 0; r < 4; r++)
        t[threadIdx.y + r * 8][threadIdx.x] = src[(size_t)(y + r * 8) * DD + x];
    __syncthreads();
    int x2 = blockIdx.y * 32 + threadIdx.x;
    int y2 = blockIdx.x * 32 + threadIdx.y;
    #pragma unroll
    for (int r = 0; r < 4; r++)
        dst[(size_t)(y2 + r * 8) * DD + x2] = t[threadIdx.x][threadIdx.y + r * 8];
}

// ---------------------------------------------------------------------------
// bf16x3 GEMM (weight prep, split-K via blockIdx.z, atomicAdd epilogue).
// BM=128 BN=256 BK=32, 256 thr, 8 warps 2x4. Output must be pre-zeroed.
// ---------------------------------------------------------------------------
#define STAGE_BYTES 49152
#define GEMM_SMEM   (2 * STAGE_BYTES)

__global__ __launch_bounds__(256, 1) void tc_gemm(
    const __nv_bfloat16* __restrict__ A0h, size_t loD,
    const __nv_bfloat16* __restrict__ Wh,
    float* __restrict__ C)
{
    extern __shared__ char smem[];
    const uint32_t sb = smem_to_u32(smem);
    const int tid = threadIdx.x;
    const int bm = blockIdx.y * 128;
    const int bn = blockIdx.x * 256;
    const int nsp = gridDim.z;
    const int cN  = 32 / nsp;
    const int cB  = blockIdx.z * cN;

    const int lr = tid >> 1;
    const int s0 = (tid & 1) * 2;
    const char* aP = (const char*)(A0h + (size_t)(bm + lr) * DD);
    const char* wP = (const char*)(Wh + (size_t)(bn + tid) * DD);
    const size_t loB  = loD * 2;
    const size_t wLoB = WU * 2;

    const uint32_t aD0 = swz(lr, s0);
    const uint32_t aD1 = swz(lr, s0 + 1);
    uint32_t wD[4];
    #pragma unroll
    for (int j = 0; j < 4; j++) wD[j] = swz(tid, j);

    const int wid = tid >> 5, lane = tid & 31;
    const int wm = wid & 1, wn = wid >> 1;
    const int rowA = wm * 64 + (lane & 15);
    const int segA = lane >> 4;
    const int xA = (rowA >> 1) & 3;
    const uint32_t aRowOff = rowA * 64;
    uint32_t aCol[2];
    aCol[0] = (uint32_t)(((segA + 0) ^ xA) << 4);
    aCol[1] = (uint32_t)(((segA + 2) ^ xA) << 4);
    const int rowB = wn * 64 + (lane & 7) + ((lane >> 4) << 3);
    const int segB = (lane >> 3) & 1;
    const int xB = (rowB >> 1) & 3;
    const uint32_t bRowOff = rowB * 64;
    uint32_t bCol[2];
    bCol[0] = (uint32_t)(((segB + 0) ^ xB) << 4);
    bCol[1] = (uint32_t)(((segB + 2) ^ xB) << 4);

    float acc[4][8][4];
    #pragma unroll
    for (int i = 0; i < 4; i++)
        #pragma unroll
        for (int j = 0; j < 8; j++)
            #pragma unroll
            for (int t = 0; t < 4; t++) acc[i][j][t] = 0.f;

    auto load_stage = [&](int c, int st) {
        uint32_t B = sb + st * STAGE_BYTES;
        size_t off = (size_t)c * 64;
        cp16(B + aD0,        aP + off + s0 * 16);
        cp16(B + aD1,        aP + off + s0 * 16 + 16);
        cp16(B + 8192 + aD0, aP + loB + off + s0 * 16);
        cp16(B + 8192 + aD1, aP + loB + off + s0 * 16 + 16);
        #pragma unroll
        for (int j = 0; j < 4; j++) {
            cp16(B + 16384 + wD[j], wP + off + j * 16);
            cp16(B + 32768 + wD[j], wP + wLoB + off + j * 16);
        }
        cp_commit();
    };

    auto do_mmas = [&](uint32_t a[4][4], uint32_t b[4][4]) {
        #pragma unroll
        for (int mi = 0; mi < 4; mi++)
            #pragma unroll
            for (int p = 0; p < 4; p++) {
                mma16816(acc[mi][2*p],   a[mi], b[p][0], b[p][1]);
                mma16816(acc[mi][2*p+1], a[mi], b[p][2], b[p][3]);
            }
    };

    auto compute_stage = [&](int st) {
        uint32_t base = sb + st * STAGE_BYTES;
        uint32_t aH = base + aRowOff;
        uint32_t aL = aH + 8192;
        uint32_t bH = base + 16384 + bRowOff;
        uint32_t bL = bH + 16384;
        #pragma unroll
        for (int k = 0; k < 2; k++) {
            uint32_t a[4][4], b[4][4];
            #pragma unroll
            for (int p = 0; p < 4; p++)
                ldsm4(bH + p * 1024 + bCol[k], b[p][0], b[p][1], b[p][2], b[p][3]);
            #pragma unroll
            for (int mi = 0; mi < 4; mi++)
                ldsm4(aH + mi * 1024 + aCol[k], a[mi][0], a[mi][1], a[mi][2], a[mi][3]);
            do_mmas(a, b);
            #pragma unroll
            for (int mi = 0; mi < 4; mi++)
                ldsm4(aL + mi * 1024 + aCol[k], a[mi][0], a[mi][1], a[mi][2], a[mi][3]);
            do_mmas(a, b);
            #pragma unroll
            for (int p = 0; p < 4; p++)
                ldsm4(bL + p * 1024 + bCol[k], b[p][0], b[p][1], b[p][2], b[p][3]);
            #pragma unroll
            for (int mi = 0; mi < 4; mi++)
                ldsm4(aH + mi * 1024 + aCol[k], a[mi][0], a[mi][1], a[mi][2], a[mi][3]);
            do_mmas(a, b);
        }
    };

    load_stage(cB, 0);
    #pragma unroll 1
    for (int i = 0; i < cN; i++) {
        int st = i & 1;
        if (i + 1 < cN) {
            load_stage(cB + i + 1, st ^ 1);
            asm volatile("cp.async.wait_group 1;" ::: "memory");
        } else {
            asm volatile("cp.async.wait_group 0;" ::: "memory");
        }
        __syncthreads();
        compute_stage(st);
        __syncthreads();
    }

    const int r0   = bm + wm * 64 + (lane >> 2);
    const int col0 = bn + wn * 64 + (lane & 3) * 2;
    #pragma unroll
    for (int nf = 0; nf < 8; nf++) {
        int col = col0 + nf * 8;
        #pragma unroll
        for (int mi = 0; mi < 4; mi++) {
            float* p0 = C + (size_t)(r0 + mi * 16) * DD + col;
            atomicAdd(p0,            acc[mi][nf][0]);
            atomicAdd(p0 + 1,        acc[mi][nf][1]);
            atomicAdd(p0 + 8*DD,     acc[mi][nf][2]);
            atomicAdd(p0 + 8*DD + 1, acc[mi][nf][3]);
        }
    }
}

// ---------------------------------------------------------------------------
// tf32 single-term GEMM, z-batched: C[z] = A[z]@W^T + bias.  (flat rows)
// ---------------------------------------------------------------------------
__global__ __launch_bounds__(256, 1) void tc_gemm_tf32(
    const float* __restrict__ A0, const float* __restrict__ A1,
    const float* __restrict__ W,
    const float* __restrict__ bias,
    float* __restrict__ C0, float* __restrict__ C1)
{
    extern __shared__ char smem[];
    const uint32_t sb = smem_to_u32(smem);
    const int tid = threadIdx.x;
    const int bm = blockIdx.y * 128;
    const int bn = blockIdx.x * 256;
    const float* A = blockIdx.z ? A1 : A0;
    float* C = blockIdx.z ? C1 : C0;

    const int lr = tid >> 1;
    const int s0 = (tid & 1) * 4;
    const char* aP = (const char*)(A + (size_t)(bm + lr) * DD);
    const char* wP = (const char*)(W + (size_t)(bn + tid) * DD);
    uint32_t aD[4], wD[8];
    #pragma unroll
    for (int j = 0; j < 4; j++) aD[j] = swzt(lr, s0 + j);
    #pragma unroll
    for (int j = 0; j < 8; j++) wD[j] = swzt(tid, j);

    const int wid = tid >> 5, lane = tid & 31;
    const int wm = wid & 1, wn = wid >> 1;
    const int tR = lane >> 2;
    const uint32_t tC4 = (uint32_t)((lane & 3) * 4);

    float acc[4][8][4];
    #pragma unroll
    for (int i = 0; i < 4; i++)
        #pragma unroll
        for (int j = 0; j < 8; j++)
            #pragma unroll
            for (int t = 0; t < 4; t++) acc[i][j][t] = 0.f;

    auto load_stage = [&](int c, int st) {
        uint32_t B = sb + st * STAGE_BYTES;
        size_t off = (size_t)c * 128;
        #pragma unroll
        for (int j = 0; j < 4; j++)
            cp16(B + aD[j], aP + off + (s0 + j) * 16);
        #pragma unroll
        for (int j = 0; j < 8; j++)
            cp16(B + 16384 + wD[j], wP + off + j * 16);
        cp_commit();
    };

    auto compute_stage = [&](int st) {
        uint32_t base = sb + st * STAGE_BYTES;
        #pragma unroll
        for (int k8 = 0; k8 < 4; k8++) {
            uint32_t bF[8][2], aF[4][4];
            #pragma unroll
            for (int nf = 0; nf < 8; nf++) {
                int n = wn * 64 + nf * 8 + tR;
                uint32_t nb = base + 16384 + n * 128 + tC4;
                bF[nf][0] = lds_tf32(nb + (((k8*2)     ^ (n & 7)) << 4));
                bF[nf][1] = lds_tf32(nb + (((k8*2 + 1) ^ (n & 7)) << 4));
            }
            #pragma unroll
            for (int mi = 0; mi < 4; mi++) {
                #pragma unroll
                for (int h = 0; h < 2; h++) {
                    int r = wm * 64 + mi * 16 + h * 8 + tR;
                    uint32_t rb = base + r * 128 + tC4;
                    aF[mi][h]     = lds_tf32(rb + (((k8*2)     ^ (r & 7)) << 4));
                    aF[mi][h + 2] = lds_tf32(rb + (((k8*2 + 1) ^ (r & 7)) << 4));
                }
            }
            #pragma unroll
            for (int mi = 0; mi < 4; mi++)
                #pragma unroll
                for (int nf = 0; nf < 8; nf++)
                    mma1688t(acc[mi][nf], aF[mi], bF[nf][0], bF[nf][1]);
        }
    };

    load_stage(0, 0);
    #pragma unroll 1
    for (int c = 0; c < 32; c++) {
        int st = c & 1;
        if (c + 1 < 32) {
            load_stage(c + 1, st ^ 1);
            asm volatile("cp.async.wait_group 1;" ::: "memory");
        } else {
            asm volatile("cp.async.wait_group 0;" ::: "memory");
        }
        __syncthreads();
        compute_stage(st);
        __syncthreads();
    }

    const int r0   = bm + wm * 64 + (lane >> 2);
    const int col0 = bn + wn * 64 + (lane & 3) * 2;
    #pragma unroll
    for (int nf = 0; nf < 8; nf++) {
        int col = col0 + nf * 8;
        float bx = bias[col], by = bias[col + 1];
        #pragma unroll
        for (int mi = 0; mi < 4; mi++) {
            float* p0 = C + (size_t)(r0 + mi * 16) * DD + col;
            float2 v0 = { acc[mi][nf][0] + bx, acc[mi][nf][1] + by };
            float2 v1 = { acc[mi][nf][2] + bx, acc[mi][nf][3] + by };
            *(float2*)p0 = v0;
            *(float2*)(p0 + 8 * DD) = v1;
        }
    }
}

// ---------------------------------------------------------------------------
// tf32 value GEMM with fused LayerNorm:
// A rows gathered from concat(raw rgb, raw tir); epilogue:
//   C[r,n] = s1[r]*acc + s2[r]*wl2[n] + b2t[n]
// ---------------------------------------------------------------------------
__global__ __launch_bounds__(256, 1) void tc_gemm_tf32_val(
    const float* __restrict__ Ar, const float* __restrict__ At,
    const float* __restrict__ W,
    float* __restrict__ C)
{
    extern __shared__ char smem[];
    const uint32_t sb = smem_to_u32(smem);
    const int tid = threadIdx.x;
    const int bm = blockIdx.y * 128;
    const int bn = blockIdx.x * 256;

    const int lr = tid >> 1;
    const int s0 = (tid & 1) * 4;
    int gr = bm + lr;
    int gbh = gr / 24, gj = gr % 24;
    const float* abase = (gj < 12) ? Ar : At;
    const char* aP = (const char*)(abase + ((size_t)gbh * 12 + (gj % 12)) * DD);
    const char* wP = (const char*)(W + (size_t)(bn + tid) * DD);
    uint32_t aD[4], wD[8];
    #pragma unroll
    for (int j = 0; j < 4; j++) aD[j] = swzt(lr, s0 + j);
    #pragma unroll
    for (int j = 0; j < 8; j++) wD[j] = swzt(tid, j);

    const int wid = tid >> 5, lane = tid & 31;
    const int wm = wid & 1, wn = wid >> 1;
    const int tR = lane >> 2;
    const uint32_t tC4 = (uint32_t)((lane & 3) * 4);

    float acc[4][8][4];
    #pragma unroll
    for (int i = 0; i < 4; i++)
        #pragma unroll
        for (int j = 0; j < 8; j++)
            #pragma unroll
            for (int t = 0; t < 4; t++) acc[i][j][t] = 0.f;

    auto load_stage = [&](int c, int st) {
        uint32_t B = sb + st * STAGE_BYTES;
        size_t off = (size_t)c * 128;
        #pragma unroll
        for (int j = 0; j < 4; j++)
            cp16(B + aD[j], aP + off + (s0 + j) * 16);
        #pragma unroll
        for (int j = 0; j < 8; j++)
            cp16(B + 16384 + wD[j], wP + off + j * 16);
        cp_commit();
    };

    auto compute_stage = [&](int st) {
        uint32_t base = sb + st * STAGE_BYTES;
        #pragma unroll
        for (int k8 = 0; k8 < 4; k8++) {
            uint32_t bF[8][2], aF[4][4];
            #pragma unroll
            for (int nf = 0; nf < 8; nf++) {
                int n = wn * 64 + nf * 8 + tR;
                uint32_t nb = base + 16384 + n * 128 + tC4;
                bF[nf][0] = lds_tf32(nb + (((k8*2)     ^ (n & 7)) << 4));
                bF[nf][1] = lds_tf32(nb + (((k8*2 + 1) ^ (n & 7)) << 4));
            }
            #pragma unroll
            for (int mi = 0; mi < 4; mi++) {
                #pragma unroll
                for (int h = 0; h < 2; h++) {
                    int r = wm * 64 + mi * 16 + h * 8 + tR;
                    uint32_t rb = base + r * 128 + tC4;
                    aF[mi][h]     = lds_tf32(rb + (((k8*2)     ^ (r & 7)) << 4));
                    aF[mi][h + 2] = lds_tf32(rb + (((k8*2 + 1) ^ (r & 7)) << 4));
                }
            }
            #pragma unroll
            for (int mi = 0; mi < 4; mi++)
                #pragma unroll
                for (int nf = 0; nf < 8; nf++)
                    mma1688t(acc[mi][nf], aF[mi], bF[nf][0], bF[nf][1]);
        }
    };

    load_stage(0, 0);
    #pragma unroll 1
    for (int c = 0; c < 32; c++) {
        int st = c & 1;
        if (c + 1 < 32) {
            load_stage(c + 1, st ^ 1);
            asm volatile("cp.async.wait_group 1;" ::: "memory");
        } else {
            asm volatile("cp.async.wait_group 0;" ::: "memory");
        }
        __syncthreads();
        compute_stage(st);
        __syncthreads();
    }

    const int r0   = bm + wm * 64 + (lane >> 2);
    const int col0 = bn + wn * 64 + (lane & 3) * 2;
    float s1v[4][2], s2v[4][2];
    #pragma unroll
    for (int mi = 0; mi < 4; mi++) {
        s1v[mi][0] = g_s1[r0 + mi * 16];     s2v[mi][0] = g_s2[r0 + mi * 16];
        s1v[mi][1] = g_s1[r0 + mi * 16 + 8]; s2v[mi][1] = g_s2[r0 + mi * 16 + 8];
    }
    #pragma unroll
    for (int nf = 0; nf < 8; nf++) {
        int col = col0 + nf * 8;
        float wx = g_wl2[col], wy = g_wl2[col + 1];
        float bx = g_b2t[col], by = g_b2t[col + 1];
        #pragma unroll
        for (int mi = 0; mi < 4; mi++) {
            float* p0 = C + (size_t)(r0 + mi * 16) * DD + col;
            float2 v0 = { s1v[mi][0]*acc[mi][nf][0] + s2v[mi][0]*wx + bx,
                          s1v[mi][0]*acc[mi][nf][1] + s2v[mi][0]*wy + by };
            float2 v1 = { s1v[mi][1]*acc[mi][nf][2] + s2v[mi][1]*wx + bx,
                          s1v[mi][1]*acc[mi][nf][3] + s2v[mi][1]*wy + by };
            *(float2*)p0 = v0;
            *(float2*)(p0 + 8 * DD) = v1;
        }
    }
}

// ---------------------------------------------------------------------------
// Bias algebra
// ---------------------------------------------------------------------------
__global__ __launch_bounds__(256) void uv_kernel(const float* __restrict__ qw,
                                                 const float* __restrict__ kw,
                                                 const float* __restrict__ qb,
                                                 const float* __restrict__ kb) {
    if (blockIdx.x < 4) {
        int d = blockIdx.x * 256 + threadIdx.x;
        float su = 0.f, sv = 0.f;
        for (int c = 0; c < DD; c++) {
            su += qw[(size_t)c * DD + d] * kb[c];
            sv += kw[(size_t)c * DD + d] * qb[c];
        }
        g_u[d] = su;
        g_v[d] = sv;
    } else {
        int tid = threadIdx.x;
        float s = qb[tid]*kb[tid] + qb[tid+256]*kb[tid+256]
                + qb[tid+512]*kb[tid+512] + qb[tid+768]*kb[tid+768];
        #pragma unroll
        for (int o = 16; o > 0; o >>= 1) s += __shfl_xor_sync(~0u, s, o);
        __shared__ float ss[8];
        if ((tid & 31) == 0) ss[tid >> 5] = s;
        __syncthreads();
        if (tid == 0) {
            float S = 0.f;
            #pragma unroll
            for (int w = 0; w < 8; w++) S += ss[w];
            g_misc[0] = S;
        }
    }
}

// t1[o] = dot(v_w[o], lnb) + vb[o];  t2[o] = dot(v_w[o], lnw)   (warp per row)
__global__ __launch_bounds__(256) void vw_gemv_kernel(const float* __restrict__ vw,
                                                      const float* __restrict__ lnw,
                                                      const float* __restrict__ lnb,
                                                      const float* __restrict__ vb) {
    int wid = threadIdx.x >> 5, lane = threadIdx.x & 31;
    int row = blockIdx.x * 8 + wid;
    const float* r = vw + (size_t)row * DD;
    float s1 = 0.f, s2 = 0.f;
    for (int c = lane; c < DD; c += 32) {
        float x = r[c];
        s1 += x * lnb[c];
        s2 += x * lnw[c];
    }
    #pragma unroll
    for (int o = 16; o > 0; o >>= 1) {
        s1 += __shfl_xor_sync(~0u, s1, o);
        s2 += __shfl_xor_sync(~0u, s2, o);
    }
    if (lane == 0) { g_t1[row] = s1 + vb[row]; g_t2[row] = s2; }
}

// wl2[n] = dot(ow[n], t2);  b2t[n] = dot(ow[n], t1)
__global__ __launch_bounds__(256) void ow_gemv_kernel(const float* __restrict__ ow) {
    int wid = threadIdx.x >> 5, lane = threadIdx.x & 31;
    int row = blockIdx.x * 8 + wid;
    const float* r = ow + (size_t)row * DD;
    float s1 = 0.f, s2 = 0.f;
    for (int c = lane; c < DD; c += 32) {
        float x = r[c];
        s1 += x * g_t1[c];
        s2 += x * g_t2[c];
    }
    #pragma unroll
    for (int o = 16; o > 0; o >>= 1) {
        s1 += __shfl_xor_sync(~0u, s1, o);
        s2 += __shfl_xor_sync(~0u, s2, o);
    }
    if (lane == 0) { g_b2t[row] = s1; g_wl2[row] = s2; }
}

// ---------------------------------------------------------------------------
// BatchNorm
// ---------------------------------------------------------------------------
__global__ void bn_zero_kernel() {
    int t = threadIdx.x;
    if (t < 24) { ((float*)g_bn_sum)[t] = 0.f; ((float*)g_bn_sq)[t] = 0.f; }
}

__global__ __launch_bounds__(256) void bn_stats_kernel(const float* __restrict__ x0,
                                                       const float* __restrict__ x1) {
    int row  = blockIdx.x;
    int sidx = blockIdx.y;
    int tid  = threadIdx.x;
    const float* x = sidx ? x1 : x0;
    float4 v = ((const float4*)(x + (size_t)row * DD))[tid];
    float s = v.x + v.y + v.z + v.w;
    float q = v.x*v.x + v.y*v.y + v.z*v.z + v.w*v.w;
    #pragma unroll
    for (int o = 16; o > 0; o >>= 1) {
        s += __shfl_xor_sync(~0u, s, o);
        q += __shfl_xor_sync(~0u, q, o);
    }
    __shared__ float ss[8], qq[8];
    if ((tid & 31) == 0) { ss[tid >> 5] = s; qq[tid >> 5] = q; }
    __syncthreads();
    if (tid == 0) {
        float S = 0.f, Q = 0.f;
        #pragma unroll
        for (int w = 0; w < 8; w++) { S += ss[w]; Q += qq[w]; }
        atomicAdd(&g_bn_sum[sidx][row % 12], S);
        atomicAdd(&g_bn_sq [sidx][row % 12], Q);
    }
}

__global__ void bn_finalize_kernel(const float* __restrict__ bn_w, const float* __restrict__ bn_b) {
    int t = threadIdx.x;
    if (t < 24) {
        int s = t / 12, c = t % 12;
        const float CNT = 3072.0f * 1024.0f;
        float mean = g_bn_sum[s][c] / CNT;
        float var  = g_bn_sq [s][c] / CNT - mean * mean;
        float rstd = rsqrtf(var + 1e-5f);
        float sc   = rstd * bn_w[c];
        g_bn_scale[s][c] = sc;
        g_bn_shift[s][c] = bn_b[c] - mean * sc;
    }
}

// in-place fp32 BN apply + pos, with fused dq/dk dots
__global__ __launch_bounds__(256) void bn_apply_dqdk_kernel(float* __restrict__ x0,
                                                            float* __restrict__ x1,
                                                            const float* __restrict__ pos) {
    int row  = blockIdx.x;
    int sidx = blockIdx.y;
    int tid  = threadIdx.x;
    float* x = sidx ? x1 : x0;
    int c = row % 12;
    int b = row / 144;
    float sc = g_bn_scale[sidx][c], sh = g_bn_shift[sidx][c];
    float4 p = ((const float4*)(pos + ((size_t)(b * 12 + c)) * DD))[tid];
    float4* xp = (float4*)(x + (size_t)row * DD) + tid;
    float4 v = *xp;
    v.x = v.x * sc + sh + p.x;
    v.y = v.y * sc + sh + p.y;
    v.z = v.z * sc + sh + p.z;
    v.w = v.w * sc + sh + p.w;
    *xp = v;
    float4 u4 = ((const float4*)g_u)[tid];
    float4 v4 = ((const float4*)g_v)[tid];
    float su = v.x*u4.x + v.y*u4.y + v.z*u4.z + v.w*u4.w;
    float sv = v.x*v4.x + v.y*v4.y + v.z*v4.z + v.w*v4.w;
    #pragma unroll
    for (int o = 16; o > 0; o >>= 1) {
        su += __shfl_xor_sync(~0u, su, o);
        sv += __shfl_xor_sync(~0u, sv, o);
    }
    __shared__ float ssu[8], ssv[8];
    if ((tid & 31) == 0) { ssu[tid >> 5] = su; ssv[tid >> 5] = sv; }
    __syncthreads();
    if (tid == 0) {
        float SU = 0.f, SV = 0.f;
        #pragma unroll
        for (int w = 0; w < 8; w++) { SU += ssu[w]; SV += ssv[w]; }
        g_dq[sidx * M1 + row] = SU;
        g_dk[sidx * M1 + row] = SV;
    }
}

// ---------------------------------------------------------------------------
// LN row stats (s1 = rstd, s2 = -mu*rstd) over concat(ar, at)
// ---------------------------------------------------------------------------
__global__ __launch_bounds__(256) void ln_stats_kernel(const float* __restrict__ ar,
                                                       const float* __restrict__ at) {
    int row = blockIdx.x;
    int tid = threadIdx.x;
    int bh = row / 24, j = row % 24;
    const float* src = (j < 12) ? ar + ((size_t)bh * 12 + j) * DD
                                : at + ((size_t)bh * 12 + (j - 12)) * DD;
    float4 v = ((const float4*)src)[tid];
    float s = v.x + v.y + v.z + v.w;
    float q = v.x*v.x + v.y*v.y + v.z*v.z + v.w*v.w;
    #pragma unroll
    for (int o = 16; o > 0; o >>= 1) {
        s += __shfl_xor_sync(~0u, s, o);
        q += __shfl_xor_sync(~0u, q, o);
    }
    __shared__ float ss[8], qq[8];
    if ((tid & 31) == 0) { ss[tid >> 5] = s; qq[tid >> 5] = q; }
    __syncthreads();
    if (tid == 0) {
        float S = 0.f, Q = 0.f;
        #pragma unroll
        for (int w = 0; w < 8; w++) { S += ss[w]; Q += qq[w]; }
        float mean = S / 1024.0f;
        float var  = Q / 1024.0f - mean * mean;
        float rstd = rsqrtf(var + 1e-5f);
        g_s1[row] = rstd;
        g_s2[row] = -mean * rstd;
    }
}

// ---------------------------------------------------------------------------
// Fused attention + output (all fp32 inputs)
// ---------------------------------------------------------------------------
#define ATTN_SMEM ((24*1024 + 24*24 + 32) * sizeof(float))

__global__ __launch_bounds__(256) void attn_out_kernel(
    const float* __restrict__ qg_r, const float* __restrict__ qg_t,
    const float* __restrict__ x_r, const float* __restrict__ x_t,
    const float* __restrict__ valp,
    const float* __restrict__ ob,
    float* __restrict__ out) {
    extern __shared__ float sm[];
    float* xs  = sm;
    float* at  = sm + 24 * 1024;
    float* dks = at + 24 * 24;

    int bh  = blockIdx.x;
    int tid = threadIdx.x;
    int warp = tid >> 5, lane = tid & 31;

    const float* xr = x_r + (size_t)bh * 12 * DD;
    const float* xt = x_t + (size_t)bh * 12 * DD;
    for (int i = tid; i < 12 * 256; i += 256) {
        ((float4*)xs)[i]            = ((const float4*)xr)[i];
        ((float4*)xs)[i + 12 * 256] = ((const float4*)xt)[i];
    }
    if (tid < 24) {
        int s = tid < 12 ? 0 : 1;
        dks[tid] = g_dk[s * M1 + bh * 12 + (tid % 12)];
    }
    __syncthreads();

    float c0v = g_misc[0];

    for (int qi = warp * 3; qi < warp * 3 + 3; qi++) {
        int s = (qi < 12) ? 0 : 1;
        const float* qrow = (s ? qg_t : qg_r) + ((size_t)bh * 12 + (qi % 12)) * DD;
        float dqv = g_dq[s * M1 + bh * 12 + (qi % 12)];
        float qv[32];
        #pragma unroll
        for (int t = 0; t < 32; t++) qv[t] = qrow[t * 32 + lane];
        for (int j = 0; j < 24; j++) {
            float sum = 0.f;
            #pragma unroll
            for (int t = 0; t < 32; t++) sum += qv[t] * xs[j * 1024 + t * 32 + lane];
            #pragma unroll
            for (int o = 16; o > 0; o >>= 1) sum += __shfl_xor_sync(~0u, sum, o);
            if (lane == 0) at[qi * 24 + j] = (sum + dqv + dks[j] + c0v) * 0.03125f;
        }
    }
    __syncthreads();

    for (int qi = warp * 3; qi < warp * 3 + 3; qi++) {
        float v = (lane < 24) ? at[qi * 24 + lane] : -3.0e38f;
        float m = v;
        #pragma unroll
        for (int o = 16; o > 0; o >>= 1) m = fmaxf(m, __shfl_xor_sync(~0u, m, o));
        float e = (lane < 24) ? expf(v - m) : 0.f;
        float s = e;
        #pragma unroll
        for (int o = 16; o > 0; o >>= 1) s += __shfl_xor_sync(~0u, s, o);
        if (lane < 24) at[qi * 24 + lane] = e / s;
    }
    __syncthreads();

    const float* vbase = valp + (size_t)bh * 24 * DD;
    for (int i = tid; i < 24 * 256; i += 256)
        ((float4*)xs)[i] = ((const float4*)vbase)[i];
    __syncthreads();

    int c0l = tid * 4;
    float4 obv = *(const float4*)(ob + c0l);
    for (int i = 0; i < 24; i++) {
        float4 acc = obv;
        #pragma unroll
        for (int j = 0; j < 24; j++) {
            float a = at[i * 24 + j];
            float4 v4 = *(const float4*)&xs[j * 1024 + c0l];
            acc.x += a * v4.x; acc.y += a * v4.y; acc.z += a * v4.z; acc.w += a * v4.w;
        }
        float* dst = out + ((i < 12) ? 0 : (size_t)M1 * DD)
                   + ((size_t)bh * 12 + (i % 12)) * DD + c0l;
        *(float4*)dst = acc;
    }
}

// ---------------------------------------------------------------------------
// Launch
// ---------------------------------------------------------------------------
extern "C" void kernel_launch(void* const* d_in, const int* in_sizes, int n_in,
                              void* d_out, int out_size) {
    const float* attn_rgb = (const float*)d_in[0];
    const float* attn_tir = (const float*)d_in[1];
    const float* pos_emb  = (const float*)d_in[2];
    const float* embed_w  = (const float*)d_in[3];
    const float* embed_b  = (const float*)d_in[4];
    const float* bn_w     = (const float*)d_in[5];
    const float* bn_b     = (const float*)d_in[6];
    const float* ln_w     = (const float*)d_in[7];
    const float* ln_b     = (const float*)d_in[8];
    const float* v_w      = (const float*)d_in[9];
    const float* v_b      = (const float*)d_in[10];
    const float* q_w      = (const float*)d_in[11];
    const float* q_b      = (const float*)d_in[12];
    const float* k_w      = (const float*)d_in[13];
    const float* k_b      = (const float*)d_in[14];
    const float* out_w    = (const float*)d_in[15];
    const float* out_b    = (const float*)d_in[16];
    float* out = (float*)d_out;

    __nv_bfloat16* wbf;
    float *f32, *wf32;
    cudaGetSymbolAddress((void**)&wbf,   g_wbf);
    cudaGetSymbolAddress((void**)&f32,   g_f32);
    cudaGetSymbolAddress((void**)&wf32,  g_wf32);

    __nv_bfloat16* qwT  = wbf + 0*WU;   // hi; lo at +WU
    __nv_bfloat16* kwT  = wbf + 2*WU;
    __nv_bfloat16* vwTL = wbf + 4*WU;
    __nv_bfloat16* oww  = wbf + 6*WU;
    float* t_qwT = wf32 + 0*WU;
    float* t_kwT = wf32 + 1*WU;
    float* t_vwT = wf32 + 2*WU;
    float* t_GT  = wf32 + 3*WU;
    float* t_W2L = wf32 + 4*WU;

    float* emb_r = f32 + 0*UU;
    float* emb_t = f32 + 1*UU;
    float* qg_r  = f32 + 2*UU;
    float* qg_t  = f32 + 3*UU;
    float* valp  = f32 + 4*UU;   // 2U

    cudaFuncSetAttribute(tc_gemm, cudaFuncAttributeMaxDynamicSharedMemorySize, GEMM_SMEM);
    cudaFuncSetAttribute(tc_gemm_tf32, cudaFuncAttributeMaxDynamicSharedMemorySize, GEMM_SMEM);
    cudaFuncSetAttribute(tc_gemm_tf32_val, cudaFuncAttributeMaxDynamicSharedMemorySize, GEMM_SMEM);
    cudaFuncSetAttribute(attn_out_kernel, cudaFuncAttributeMaxDynamicSharedMemorySize, (int)ATTN_SMEM);

    dim3 g1z(4, M1 / 128, 2);
    dim3 g2(4, M2 / 128, 1);
    dim3 gwk(4, 8, 4);           // split-K weight GEMMs
    dim3 gbn(M1, 2);
    dim3 gt(32, 32, 3), bt(32, 8);
    dim3 gcv((int)(WU/1024), 4);

    // ---- weight preprocessing ----
    transpose3_kernel<<<gt, bt>>>(q_w, k_w, v_w, t_qwT, t_kwT, t_vwT);
    wcvt4_kernel<<<gcv, 256>>>(t_qwT, t_kwT, t_vwT, out_w, ln_w, qwT, kwT, vwTL, oww);
    cudaMemsetAsync(t_GT, 0, 2 * WU * sizeof(float));   // t_GT + t_W2L contiguous
    tc_gemm<<<gwk, 256, GEMM_SMEM>>>(kwT, WU, qwT, t_GT);    // GT = kw^T@qw
    tc_gemm<<<gwk, 256, GEMM_SMEM>>>(oww, WU, vwTL, t_W2L);  // W2L = ow@vw (lnw-folded)
    vw_gemv_kernel<<<128, 256>>>(v_w, ln_w, ln_b, v_b);
    ow_gemv_kernel<<<128, 256>>>(out_w);
    uv_kernel<<<5, 256>>>(q_w, k_w, q_b, k_b);

    // ---- embedding GEMMs (tf32, z-batched) ----
    tc_gemm_tf32<<<g1z, 256, GEMM_SMEM>>>(attn_rgb, attn_tir, embed_w, embed_b, emb_r, emb_t);

    // ---- BatchNorm + pos (+ fused dq/dk), in-place fp32 ----
    bn_zero_kernel<<<1, 32>>>();
    bn_stats_kernel<<<gbn, 256>>>(emb_r, emb_t);
    bn_finalize_kernel<<<1, 32>>>(bn_w, bn_b);
    bn_apply_dqdk_kernel<<<gbn, 256>>>(emb_r, emb_t, pos_emb);

    // ---- LN stats + fused-LN value' GEMM ----
    ln_stats_kernel<<<M2, 256>>>(attn_rgb, attn_tir);
    tc_gemm_tf32_val<<<g2, 256, GEMM_SMEM>>>(attn_rgb, attn_tir, t_W2L, valp);

    // ---- qg projections (tf32, z-batched) ----
    tc_gemm_tf32<<<g1z, 256, GEMM_SMEM>>>(emb_r, emb_t, t_GT, g_zeros, qg_r, qg_t);

    // ---- attention + direct output ----
    attn_out_kernel<<<BH, 256, ATTN_SMEM>>>(qg_r, qg_t, emb_r, emb_t, valp, out_b, out);
}